// round 1
// baseline (speedup 1.0000x reference)
#include <cuda_runtime.h>
#include <math.h>

// Problem constants
constexpr int Bb = 2;
constexpr int Nn = 4096;
constexpr int Cc = 256;
constexpr int Hh = 8;
constexpr int Dh = 32;
constexpr int Mm = 1024;      // reduced tokens (32x32)
constexpr int Kc = 1024;      // conv-as-GEMM K (4 * 256)

// -------- scratch (static device allocations; no cudaMalloc allowed) --------
__device__ float g_q   [Bb * Nn * Cc];        // 8 MB   q = x1 @ q_w^T
__device__ float g_gath[2 * Bb * Mm * Kc];    // 16 MB  gathered conv patches
__device__ float g_srw [Cc * Kc];             // 1 MB   packed sr_w [co][seg*256+ci]
__device__ float g_xr  [2 * Bb * Mm * Cc];    // 4 MB   [src][b][m][c], post-LN
__device__ float g_k2  [Bb * Mm * Cc];        // 2 MB   keys from x2r
__device__ float g_v1  [Bb * Mm * Cc];        // 2 MB   values from x1r
__device__ float g_attn[Bb * Nn * Cc];        // 8 MB   attention output (pre-proj)

// ---------------------------------------------------------------------------
// Pack sr_w [co][ci][kh][kw] -> [co][ (kh*2+kw)*256 + ci ]  (k-major for GEMM)
// ---------------------------------------------------------------------------
__global__ void pack_srw_kernel(const float* __restrict__ srw) {
    int idx = blockIdx.x * 256 + threadIdx.x;      // 256*1024 total
    int co = idx >> 10;
    int k  = idx & 1023;
    int seg = k >> 8;        // kh*2+kw
    int ci  = k & 255;
    g_srw[idx] = srw[((co << 8) + ci) * 4 + seg];
}

// ---------------------------------------------------------------------------
// Gather conv patches: row R = src*2048 + b*1024 + m ; col k = seg*256 + ci
// value = x_src[b][ (2i+kh)*64 + 2j+kw ][ci],  m = i*32 + j
// ---------------------------------------------------------------------------
__global__ void gather_kernel(const float* __restrict__ x1,
                              const float* __restrict__ x2) {
    unsigned idx = blockIdx.x * 256 + threadIdx.x;   // float4 index, 2^20 total
    int k4  = idx & 255;
    int m   = (idx >> 8) & 1023;
    int b   = (idx >> 18) & 1;
    int src = (idx >> 19) & 1;
    int seg = k4 >> 6;           // k/256
    int ci4 = k4 & 63;
    int i = m >> 5, j = m & 31;
    int kh = seg >> 1, kw = seg & 1;
    int n = (2 * i + kh) * 64 + 2 * j + kw;
    const float* sp = src ? x2 : x1;
    float4 v = *(const float4*)(sp + ((long)b * Nn + n) * Cc + ci4 * 4);
    ((float4*)g_gath)[idx] = v;
}

// ---------------------------------------------------------------------------
// Generic GEMM: C[m,n] = sum_k A[m,k] * W[n,k] (+ bias[n])
// BM=128, BN=64, BK=32, 256 threads, 8x4 per thread. Requires M%128==0, N%64==0, K%32==0.
// ---------------------------------------------------------------------------
__global__ __launch_bounds__(256) void gemm_wt_kernel(
    const float* __restrict__ A, const float* __restrict__ W,
    const float* __restrict__ bias, float* __restrict__ Cout,
    int Mtot, int Ndim, int K)
{
    __shared__ float As[32][132];   // [k][m], padded; 132*4=528 (16B aligned rows)
    __shared__ float Ws[32][68];    // [k][n], padded

    int tid = threadIdx.x;
    int tx = tid & 15, ty = tid >> 4;
    int m0 = blockIdx.x * 128;
    int n0 = blockIdx.y * 64;

    float acc[8][4];
#pragma unroll
    for (int i = 0; i < 8; i++)
#pragma unroll
        for (int j = 0; j < 4; j++) acc[i][j] = 0.f;

    for (int k0 = 0; k0 < K; k0 += 32) {
        // load A tile 128x32 (1024 float4 / 256 thr = 4 each), store transposed
#pragma unroll
        for (int i = 0; i < 4; i++) {
            int id = tid + i * 256;
            int row = id >> 3, c4 = id & 7;
            float4 v = *(const float4*)(A + (long)(m0 + row) * K + k0 + c4 * 4);
            As[c4 * 4 + 0][row] = v.x;
            As[c4 * 4 + 1][row] = v.y;
            As[c4 * 4 + 2][row] = v.z;
            As[c4 * 4 + 3][row] = v.w;
        }
        // load W tile 64x32 (512 float4 / 256 thr = 2 each), transposed
#pragma unroll
        for (int i = 0; i < 2; i++) {
            int id = tid + i * 256;
            int row = id >> 3, c4 = id & 7;
            float4 v = *(const float4*)(W + (long)(n0 + row) * K + k0 + c4 * 4);
            Ws[c4 * 4 + 0][row] = v.x;
            Ws[c4 * 4 + 1][row] = v.y;
            Ws[c4 * 4 + 2][row] = v.z;
            Ws[c4 * 4 + 3][row] = v.w;
        }
        __syncthreads();
#pragma unroll
        for (int k = 0; k < 32; k++) {
            float4 a0 = *(float4*)&As[k][ty * 8];
            float4 a1 = *(float4*)&As[k][ty * 8 + 4];
            float4 w0 = *(float4*)&Ws[k][tx * 4];
            float a[8] = {a0.x, a0.y, a0.z, a0.w, a1.x, a1.y, a1.z, a1.w};
            float w[4] = {w0.x, w0.y, w0.z, w0.w};
#pragma unroll
            for (int i = 0; i < 8; i++)
#pragma unroll
                for (int j = 0; j < 4; j++)
                    acc[i][j] = fmaf(a[i], w[j], acc[i][j]);
        }
        __syncthreads();
    }

    float bsv[4] = {0.f, 0.f, 0.f, 0.f};
    if (bias) {
#pragma unroll
        for (int j = 0; j < 4; j++) bsv[j] = bias[n0 + tx * 4 + j];
    }
#pragma unroll
    for (int i = 0; i < 8; i++) {
        long m = m0 + ty * 8 + i;
        float4 o;
        o.x = acc[i][0] + bsv[0];
        o.y = acc[i][1] + bsv[1];
        o.z = acc[i][2] + bsv[2];
        o.w = acc[i][3] + bsv[3];
        *(float4*)(Cout + m * Ndim + n0 + tx * 4) = o;
    }
}

// ---------------------------------------------------------------------------
// LayerNorm over rows of g_xr (4096 rows x 256), in place. One warp per row.
// ---------------------------------------------------------------------------
__global__ __launch_bounds__(256) void layernorm_kernel(
    const float* __restrict__ g, const float* __restrict__ b)
{
    int warp = threadIdx.x >> 5, lane = threadIdx.x & 31;
    long row = (long)blockIdx.x * 8 + warp;
    float* p = g_xr + row * 256;

    float4 v0 = ((float4*)p)[lane];
    float4 v1 = ((float4*)p)[lane + 32];
    float s  = v0.x + v0.y + v0.z + v0.w + v1.x + v1.y + v1.z + v1.w;
    float sq = v0.x * v0.x + v0.y * v0.y + v0.z * v0.z + v0.w * v0.w +
               v1.x * v1.x + v1.y * v1.y + v1.z * v1.z + v1.w * v1.w;
#pragma unroll
    for (int off = 16; off; off >>= 1) {
        s  += __shfl_xor_sync(0xffffffffu, s, off);
        sq += __shfl_xor_sync(0xffffffffu, sq, off);
    }
    float mu = s * (1.f / 256.f);
    float var = sq * (1.f / 256.f) - mu * mu;
    float rs = rsqrtf(var + 1e-5f);

    int c0 = lane * 4;
    float4 g0 = ((const float4*)g)[lane];
    float4 b0 = ((const float4*)b)[lane];
    float4 g1 = ((const float4*)g)[lane + 32];
    float4 b1 = ((const float4*)b)[lane + 32];
    (void)c0;
    float4 o0, o1;
    o0.x = (v0.x - mu) * rs * g0.x + b0.x;
    o0.y = (v0.y - mu) * rs * g0.y + b0.y;
    o0.z = (v0.z - mu) * rs * g0.z + b0.z;
    o0.w = (v0.w - mu) * rs * g0.w + b0.w;
    o1.x = (v1.x - mu) * rs * g1.x + b1.x;
    o1.y = (v1.y - mu) * rs * g1.y + b1.y;
    o1.z = (v1.z - mu) * rs * g1.z + b1.z;
    o1.w = (v1.w - mu) * rs * g1.w + b1.w;
    ((float4*)p)[lane] = o0;
    ((float4*)p)[lane + 32] = o1;
}

// ---------------------------------------------------------------------------
// Flash attention: per block = (128 q rows, one (b,h)). K/V chunks of 32.
// Q is pre-scaled by 1/sqrt(Dh) at load. Online softmax.
// Thread map: 16x16 (ty=rows: 8 each; tx=cols: 2 each).
// ---------------------------------------------------------------------------
__global__ __launch_bounds__(256) void attention_kernel() {
    __shared__ float Qs[32][132];   // [d][r], scaled
    __shared__ float Ks[32][36];    // [d][m_chunk]
    __shared__ float Vs[32][32];    // [m_chunk][d]
    __shared__ float Ps[32][132];   // [m_chunk][r]

    int tid = threadIdx.x;
    int tx = tid & 15, ty = tid >> 4;
    int n0 = blockIdx.x * 128;
    int h  = blockIdx.y;
    int b  = blockIdx.z;

    const float* Qg = g_q  + ((long)b * Nn + n0) * Cc + h * 32;
    const float* Kg = g_k2 + (long)b * Mm * Cc + h * 32;
    const float* Vg = g_v1 + (long)b * Mm * Cc + h * 32;
    const float scale = 0.17677669529663689f;  // 1/sqrt(32)

    // Load Q tile 128x32 transposed + prescale
#pragma unroll
    for (int i = 0; i < 4; i++) {
        int id = tid + i * 256;
        int row = id >> 3, c4 = id & 7;
        float4 v = *(const float4*)(Qg + (long)row * Cc + c4 * 4);
        Qs[c4 * 4 + 0][row] = v.x * scale;
        Qs[c4 * 4 + 1][row] = v.y * scale;
        Qs[c4 * 4 + 2][row] = v.z * scale;
        Qs[c4 * 4 + 3][row] = v.w * scale;
    }
    __syncthreads();

    float mrun[8], lrun[8], O[8][2];
#pragma unroll
    for (int i = 0; i < 8; i++) {
        mrun[i] = -1e30f; lrun[i] = 0.f; O[i][0] = 0.f; O[i][1] = 0.f;
    }

    for (int mc = 0; mc < Mm / 32; mc++) {
        // load K,V chunk (32 rows x 32 floats each): 1 float4 each per thread
        {
            int row = tid >> 3, c4 = tid & 7;
            float4 kv = *(const float4*)(Kg + (long)(mc * 32 + row) * Cc + c4 * 4);
            Ks[c4 * 4 + 0][row] = kv.x;
            Ks[c4 * 4 + 1][row] = kv.y;
            Ks[c4 * 4 + 2][row] = kv.z;
            Ks[c4 * 4 + 3][row] = kv.w;
            float4 vv = *(const float4*)(Vg + (long)(mc * 32 + row) * Cc + c4 * 4);
            *(float4*)&Vs[row][c4 * 4] = vv;
        }
        __syncthreads();

        // S = Q @ K^T (chunk): s[8][2]
        float s[8][2];
#pragma unroll
        for (int i = 0; i < 8; i++) { s[i][0] = 0.f; s[i][1] = 0.f; }
#pragma unroll
        for (int k = 0; k < 32; k++) {
            float4 a0 = *(float4*)&Qs[k][ty * 8];
            float4 a1 = *(float4*)&Qs[k][ty * 8 + 4];
            float k0 = Ks[k][tx * 2], k1 = Ks[k][tx * 2 + 1];
            float a[8] = {a0.x, a0.y, a0.z, a0.w, a1.x, a1.y, a1.z, a1.w};
#pragma unroll
            for (int i = 0; i < 8; i++) {
                s[i][0] = fmaf(a[i], k0, s[i][0]);
                s[i][1] = fmaf(a[i], k1, s[i][1]);
            }
        }

        // online softmax (reduce across the 16-lane tx group)
#pragma unroll
        for (int i = 0; i < 8; i++) {
            float mx = fmaxf(s[i][0], s[i][1]);
#pragma unroll
            for (int off = 8; off; off >>= 1)
                mx = fmaxf(mx, __shfl_xor_sync(0xffffffffu, mx, off));
            float mnew = fmaxf(mrun[i], mx);
            float p0 = __expf(s[i][0] - mnew);
            float p1 = __expf(s[i][1] - mnew);
            float alpha = __expf(mrun[i] - mnew);
            mrun[i] = mnew;
            float rs = p0 + p1;
#pragma unroll
            for (int off = 8; off; off >>= 1)
                rs += __shfl_xor_sync(0xffffffffu, rs, off);
            lrun[i] = lrun[i] * alpha + rs;
            O[i][0] *= alpha;
            O[i][1] *= alpha;
            Ps[tx * 2 + 0][ty * 8 + i] = p0;
            Ps[tx * 2 + 1][ty * 8 + i] = p1;
        }
        __syncthreads();

        // O += P @ V
#pragma unroll
        for (int c = 0; c < 32; c++) {
            float4 p0 = *(float4*)&Ps[c][ty * 8];
            float4 p1 = *(float4*)&Ps[c][ty * 8 + 4];
            float v0 = Vs[c][tx * 2], v1 = Vs[c][tx * 2 + 1];
            float p[8] = {p0.x, p0.y, p0.z, p0.w, p1.x, p1.y, p1.z, p1.w};
#pragma unroll
            for (int i = 0; i < 8; i++) {
                O[i][0] = fmaf(p[i], v0, O[i][0]);
                O[i][1] = fmaf(p[i], v1, O[i][1]);
            }
        }
        __syncthreads();
    }

    // epilogue
    float* Og = g_attn + ((long)b * Nn + n0) * Cc + h * 32;
#pragma unroll
    for (int i = 0; i < 8; i++) {
        float inv = 1.f / lrun[i];
        float2 o = make_float2(O[i][0] * inv, O[i][1] * inv);
        *(float2*)(Og + (long)(ty * 8 + i) * Cc + tx * 2) = o;
    }
}

// ---------------------------------------------------------------------------
extern "C" void kernel_launch(void* const* d_in, const int* in_sizes, int n_in,
                              void* d_out, int out_size) {
    const float* x1     = (const float*)d_in[0];
    const float* x2     = (const float*)d_in[1];
    const float* q_w    = (const float*)d_in[2];
    const float* kv_w   = (const float*)d_in[3];
    const float* sr_w   = (const float*)d_in[4];
    const float* sr_b   = (const float*)d_in[5];
    const float* ln_g   = (const float*)d_in[6];
    const float* ln_b   = (const float*)d_in[7];
    const float* proj_w = (const float*)d_in[8];
    const float* proj_b = (const float*)d_in[9];
    float* out = (float*)d_out;

    float* p_q;    cudaGetSymbolAddress((void**)&p_q, g_q);
    float* p_gath; cudaGetSymbolAddress((void**)&p_gath, g_gath);
    float* p_srw;  cudaGetSymbolAddress((void**)&p_srw, g_srw);
    float* p_xr;   cudaGetSymbolAddress((void**)&p_xr, g_xr);
    float* p_k2;   cudaGetSymbolAddress((void**)&p_k2, g_k2);
    float* p_v1;   cudaGetSymbolAddress((void**)&p_v1, g_v1);
    float* p_attn; cudaGetSymbolAddress((void**)&p_attn, g_attn);

    // 1) pack conv weights
    pack_srw_kernel<<<1024, 256>>>(sr_w);
    // 2) gather conv patches for both inputs
    gather_kernel<<<4096, 256>>>(x1, x2);
    // 3) q = x1 @ q_w^T     [8192,256]
    gemm_wt_kernel<<<dim3(64, 4), 256>>>(x1, q_w, nullptr, p_q, Bb * Nn, Cc, Cc);
    // 4) sr conv as GEMM: [4096,1024] @ [256,1024]^T + sr_b
    gemm_wt_kernel<<<dim3(32, 4), 256>>>(p_gath, p_srw, sr_b, p_xr,
                                         2 * Bb * Mm, Cc, Kc);
    // 5) layernorm (in place on g_xr)
    layernorm_kernel<<<512, 256>>>(ln_g, ln_b);
    // 6) k2 = x2r @ kv_w[0:256]^T ; v1 = x1r @ kv_w[256:512]^T
    gemm_wt_kernel<<<dim3(16, 4), 256>>>(p_xr + (long)Bb * Mm * Cc, kv_w,
                                         nullptr, p_k2, Bb * Mm, Cc, Cc);
    gemm_wt_kernel<<<dim3(16, 4), 256>>>(p_xr, kv_w + Cc * Cc,
                                         nullptr, p_v1, Bb * Mm, Cc, Cc);
    // 7) flash attention -> g_attn
    attention_kernel<<<dim3(Nn / 128, Hh, Bb), 256>>>();
    // 8) out = g_attn @ proj_w^T + proj_b
    gemm_wt_kernel<<<dim3(64, 4), 256>>>(p_attn, proj_w, proj_b, out,
                                         Bb * Nn, Cc, Cc);
}

// round 3
// speedup vs baseline: 1.1526x; 1.1526x over previous
#include <cuda_runtime.h>
#include <cuda_bf16.h>
#include <cstdint>
#include <math.h>

// Problem constants
constexpr int Bb = 2;
constexpr int Nn = 4096;
constexpr int Cc = 256;
constexpr int Hh = 8;
constexpr int Mm = 1024;      // reduced tokens (32x32)
constexpr int Kc = 1024;      // conv-as-GEMM K (4 * 256)

// -------- scratch (static device allocations; no cudaMalloc allowed) --------
__device__ float g_q   [Bb * Nn * Cc];          // fp32 q (read by attention)
__device__ float g_xr  [2 * Bb * Mm * Cc];      // fp32 conv output (pre-LN)
__device__ float g_k2  [Bb * Mm * Cc];          // fp32 keys (attention)
__device__ float g_v1  [Bb * Mm * Cc];          // fp32 values (attention)

__device__ __nv_bfloat16 g_x1h [Bb * Nn * Cc];      // x1 split
__device__ __nv_bfloat16 g_x1l [Bb * Nn * Cc];
__device__ __nv_bfloat16 g_gah [2 * Bb * Mm * Kc];  // gathered patches split
__device__ __nv_bfloat16 g_gal [2 * Bb * Mm * Kc];
__device__ __nv_bfloat16 g_srh [Cc * Kc];           // packed sr_w split
__device__ __nv_bfloat16 g_srl [Cc * Kc];
__device__ __nv_bfloat16 g_xrh [2 * Bb * Mm * Cc];  // post-LN split
__device__ __nv_bfloat16 g_xrl [2 * Bb * Mm * Cc];
__device__ __nv_bfloat16 g_ath [Bb * Nn * Cc];      // attention out split
__device__ __nv_bfloat16 g_atl [Bb * Nn * Cc];
__device__ __nv_bfloat16 g_qwh [Cc * Cc];
__device__ __nv_bfloat16 g_qwl [Cc * Cc];
__device__ __nv_bfloat16 g_kwh [2 * Cc * Cc];
__device__ __nv_bfloat16 g_kwl [2 * Cc * Cc];
__device__ __nv_bfloat16 g_pwh [Cc * Cc];
__device__ __nv_bfloat16 g_pwl [Cc * Cc];

// ---------------------------------------------------------------------------
__device__ __forceinline__ uint32_t smem_u32(const void* p) {
    uint32_t a;
    asm("{ .reg .u64 t; cvta.to.shared.u64 t, %1; cvt.u32.u64 %0, t; }"
        : "=r"(a) : "l"(p));
    return a;
}
__device__ __forceinline__ void split2(float v, __nv_bfloat16& h, __nv_bfloat16& l) {
    h = __float2bfloat16(v);
    l = __float2bfloat16(v - __bfloat162float(h));
}

#define LDSM_X4(r0, r1, r2, r3, addr) \
    asm volatile("ldmatrix.sync.aligned.m8n8.x4.shared.b16 {%0,%1,%2,%3}, [%4];" \
                 : "=r"(r0), "=r"(r1), "=r"(r2), "=r"(r3) : "r"(addr))

#define MMA_BF16(c, a, b) \
    asm volatile("mma.sync.aligned.m16n8k16.row.col.f32.bf16.bf16.f32 " \
                 "{%0,%1,%2,%3}, {%4,%5,%6,%7}, {%8,%9}, {%0,%1,%2,%3};" \
                 : "+f"((c)[0]), "+f"((c)[1]), "+f"((c)[2]), "+f"((c)[3]) \
                 : "r"((a)[0]), "r"((a)[1]), "r"((a)[2]), "r"((a)[3]), \
                   "r"((b)[0]), "r"((b)[1]))

// ---------------------------------------------------------------------------
// Pack sr_w [co][ci][kh][kw] -> hi/lo bf16 [co][ seg*256 + ci ]
// ---------------------------------------------------------------------------
__global__ void pack_srw_kernel(const float* __restrict__ srw) {
    int idx = blockIdx.x * 256 + threadIdx.x;      // 256*1024 total
    int co = idx >> 10;
    int k  = idx & 1023;
    int seg = k >> 8;
    int ci  = k & 255;
    float v = srw[((co << 8) + ci) * 4 + seg];
    __nv_bfloat16 h, l;
    split2(v, h, l);
    g_srh[idx] = h;
    g_srl[idx] = l;
}

// ---------------------------------------------------------------------------
// Gather conv patches -> hi/lo bf16
// ---------------------------------------------------------------------------
__global__ void gather_kernel(const float* __restrict__ x1,
                              const float* __restrict__ x2) {
    unsigned idx = blockIdx.x * 256 + threadIdx.x;   // float4 index, 2^20 total
    int k4  = idx & 255;
    int m   = (idx >> 8) & 1023;
    int b   = (idx >> 18) & 1;
    int src = (idx >> 19) & 1;
    int seg = k4 >> 6;
    int ci4 = k4 & 63;
    int i = m >> 5, j = m & 31;
    int kh = seg >> 1, kw = seg & 1;
    int n = (2 * i + kh) * 64 + 2 * j + kw;
    const float* sp = src ? x2 : x1;
    float4 v = *(const float4*)(sp + ((long)b * Nn + n) * Cc + ci4 * 4);
    __nv_bfloat16 h0, h1, h2, h3, l0, l1, l2, l3;
    split2(v.x, h0, l0); split2(v.y, h1, l1);
    split2(v.z, h2, l2); split2(v.w, h3, l3);
    __nv_bfloat162 ph0; ph0.x = h0; ph0.y = h1;
    __nv_bfloat162 ph1; ph1.x = h2; ph1.y = h3;
    __nv_bfloat162 pl0; pl0.x = l0; pl0.y = l1;
    __nv_bfloat162 pl1; pl1.x = l2; pl1.y = l3;
    ((__nv_bfloat162*)g_gah)[idx * 2]     = ph0;
    ((__nv_bfloat162*)g_gah)[idx * 2 + 1] = ph1;
    ((__nv_bfloat162*)g_gal)[idx * 2]     = pl0;
    ((__nv_bfloat162*)g_gal)[idx * 2 + 1] = pl1;
}

// ---------------------------------------------------------------------------
// Generic fp32 -> (hi,lo) bf16 split, float4 vectorized. n4 = n/4 float4s.
// ---------------------------------------------------------------------------
__global__ void split_kernel(const float* __restrict__ in,
                             __nv_bfloat16* __restrict__ oh,
                             __nv_bfloat16* __restrict__ ol, int n4) {
    int idx = blockIdx.x * 256 + threadIdx.x;
    if (idx >= n4) return;
    float4 v = ((const float4*)in)[idx];
    __nv_bfloat16 h0, h1, h2, h3, l0, l1, l2, l3;
    split2(v.x, h0, l0); split2(v.y, h1, l1);
    split2(v.z, h2, l2); split2(v.w, h3, l3);
    __nv_bfloat162 ph0; ph0.x = h0; ph0.y = h1;
    __nv_bfloat162 ph1; ph1.x = h2; ph1.y = h3;
    __nv_bfloat162 pl0; pl0.x = l0; pl0.y = l1;
    __nv_bfloat162 pl1; pl1.x = l2; pl1.y = l3;
    ((__nv_bfloat162*)oh)[idx * 2]     = ph0;
    ((__nv_bfloat162*)oh)[idx * 2 + 1] = ph1;
    ((__nv_bfloat162*)ol)[idx * 2]     = pl0;
    ((__nv_bfloat162*)ol)[idx * 2 + 1] = pl1;
}

// ---------------------------------------------------------------------------
// mma.sync GEMM, bf16x2 split emulation of fp32.
// C[m,n] = sum_k A[m,k]*W[n,k] (+bias[n]), CTA tile 128x64, BK=32.
// 8 warps in 4(m) x 2(n); warp tile 32x32 = 2x4 mma m16n8k16 tiles.
// 3 passes per k-step: hi*hi + hi*lo + lo*hi.
// ---------------------------------------------------------------------------
constexpr int AST = 40;   // smem stride in halves (80B rows: ldmatrix conflict-free)

__global__ __launch_bounds__(256) void gemm_mma_kernel(
    const __nv_bfloat16* __restrict__ Ah, const __nv_bfloat16* __restrict__ Al,
    const __nv_bfloat16* __restrict__ Wh, const __nv_bfloat16* __restrict__ Wl,
    const float* __restrict__ bias, float* __restrict__ Cout,
    int Ndim, int K)
{
    __shared__ __nv_bfloat16 sAh[128 * AST], sAl[128 * AST];
    __shared__ __nv_bfloat16 sWh[64 * AST],  sWl[64 * AST];
    __shared__ float sbias[64];

    int tid = threadIdx.x, lane = tid & 31, wid = tid >> 5;
    int wm = wid >> 1, wn = wid & 1;
    int m0 = blockIdx.x * 128, n0 = blockIdx.y * 64;

    if (tid < 64) sbias[tid] = bias ? bias[n0 + tid] : 0.f;

    float acc[2][4][4];
#pragma unroll
    for (int mt = 0; mt < 2; mt++)
#pragma unroll
        for (int nt = 0; nt < 4; nt++)
#pragma unroll
            for (int e = 0; e < 4; e++) acc[mt][nt][e] = 0.f;

    // ldmatrix per-lane addressing
    int a_row  = wm * 32 + (lane & 15);
    int a_colb = (lane >> 4) << 3;
    int b_row  = wn * 32 + ((lane >> 4) << 3) + (lane & 7);
    int b_colb = ((lane >> 3) & 1) << 3;

    uint32_t sa_h = smem_u32(sAh), sa_l = smem_u32(sAl);
    uint32_t sb_h = smem_u32(sWh), sb_l = smem_u32(sWl);

    // global tile load mapping
    int ar = tid >> 1, ahalf = tid & 1;     // A: 2 thr/row, 16 halves each
    int brr = tid >> 2, bq = tid & 3;       // W: 4 thr/row, 8 halves each

    for (int k0 = 0; k0 < K; k0 += 32) {
        {
            size_t ga = (size_t)(m0 + ar) * K + k0 + ahalf * 16;
            const uint4* pAh = (const uint4*)(Ah + ga);
            const uint4* pAl = (const uint4*)(Al + ga);
            *(uint4*)&sAh[ar * AST + ahalf * 16]     = pAh[0];
            *(uint4*)&sAh[ar * AST + ahalf * 16 + 8] = pAh[1];
            *(uint4*)&sAl[ar * AST + ahalf * 16]     = pAl[0];
            *(uint4*)&sAl[ar * AST + ahalf * 16 + 8] = pAl[1];
            size_t gb = (size_t)(n0 + brr) * K + k0 + bq * 8;
            *(uint4*)&sWh[brr * AST + bq * 8] = *(const uint4*)(Wh + gb);
            *(uint4*)&sWl[brr * AST + bq * 8] = *(const uint4*)(Wl + gb);
        }
        __syncthreads();

#pragma unroll
        for (int ks = 0; ks < 32; ks += 16) {
            uint32_t aH[2][4], aL[2][4], bH[4][2], bL[4][2];
#pragma unroll
            for (int mt = 0; mt < 2; mt++) {
                uint32_t off = (uint32_t)(((a_row + mt * 16) * AST + ks + a_colb) * 2);
                LDSM_X4(aH[mt][0], aH[mt][1], aH[mt][2], aH[mt][3], sa_h + off);
                LDSM_X4(aL[mt][0], aL[mt][1], aL[mt][2], aL[mt][3], sa_l + off);
            }
#pragma unroll
            for (int p = 0; p < 2; p++) {
                uint32_t off = (uint32_t)(((b_row + p * 16) * AST + ks + b_colb) * 2);
                uint32_t r0, r1, r2, r3;
                LDSM_X4(r0, r1, r2, r3, sb_h + off);
                bH[p * 2][0] = r0; bH[p * 2][1] = r1;
                bH[p * 2 + 1][0] = r2; bH[p * 2 + 1][1] = r3;
                LDSM_X4(r0, r1, r2, r3, sb_l + off);
                bL[p * 2][0] = r0; bL[p * 2][1] = r1;
                bL[p * 2 + 1][0] = r2; bL[p * 2 + 1][1] = r3;
            }
#pragma unroll
            for (int mt = 0; mt < 2; mt++)
#pragma unroll
                for (int nt = 0; nt < 4; nt++) {
                    MMA_BF16(acc[mt][nt], aH[mt], bH[nt]);
                    MMA_BF16(acc[mt][nt], aH[mt], bL[nt]);
                    MMA_BF16(acc[mt][nt], aL[mt], bH[nt]);
                }
        }
        __syncthreads();
    }

    // epilogue
    int g = lane >> 2, tig = lane & 3;
#pragma unroll
    for (int mt = 0; mt < 2; mt++)
#pragma unroll
        for (int hf = 0; hf < 2; hf++) {
            int row = m0 + wm * 32 + mt * 16 + g + hf * 8;
#pragma unroll
            for (int nt = 0; nt < 4; nt++) {
                int cb = wn * 32 + nt * 8 + tig * 2;
                float2 o;
                o.x = acc[mt][nt][hf * 2 + 0] + sbias[cb];
                o.y = acc[mt][nt][hf * 2 + 1] + sbias[cb + 1];
                *(float2*)(Cout + (size_t)row * Ndim + n0 + cb) = o;
            }
        }
}

// ---------------------------------------------------------------------------
// LayerNorm over rows of g_xr (4096 x 256); writes bf16 hi/lo splits.
// ---------------------------------------------------------------------------
__global__ __launch_bounds__(256) void layernorm_kernel(
    const float* __restrict__ g, const float* __restrict__ b)
{
    int warp = threadIdx.x >> 5, lane = threadIdx.x & 31;
    long row = (long)blockIdx.x * 8 + warp;
    const float* p = g_xr + row * 256;

    float4 v0 = ((const float4*)p)[lane];
    float4 v1 = ((const float4*)p)[lane + 32];
    float s  = v0.x + v0.y + v0.z + v0.w + v1.x + v1.y + v1.z + v1.w;
    float sq = v0.x * v0.x + v0.y * v0.y + v0.z * v0.z + v0.w * v0.w +
               v1.x * v1.x + v1.y * v1.y + v1.z * v1.z + v1.w * v1.w;
#pragma unroll
    for (int off = 16; off; off >>= 1) {
        s  += __shfl_xor_sync(0xffffffffu, s, off);
        sq += __shfl_xor_sync(0xffffffffu, sq, off);
    }
    float mu = s * (1.f / 256.f);
    float var = sq * (1.f / 256.f) - mu * mu;
    float rs = rsqrtf(var + 1e-5f);

    float4 g0 = ((const float4*)g)[lane];
    float4 b0 = ((const float4*)b)[lane];
    float4 g1 = ((const float4*)g)[lane + 32];
    float4 b1 = ((const float4*)b)[lane + 32];
    float o[8];
    o[0] = (v0.x - mu) * rs * g0.x + b0.x;
    o[1] = (v0.y - mu) * rs * g0.y + b0.y;
    o[2] = (v0.z - mu) * rs * g0.z + b0.z;
    o[3] = (v0.w - mu) * rs * g0.w + b0.w;
    o[4] = (v1.x - mu) * rs * g1.x + b1.x;
    o[5] = (v1.y - mu) * rs * g1.y + b1.y;
    o[6] = (v1.z - mu) * rs * g1.z + b1.z;
    o[7] = (v1.w - mu) * rs * g1.w + b1.w;

    long e0 = row * 256 + lane * 4;
    long e1 = row * 256 + (lane + 32) * 4;
#pragma unroll
    for (int half = 0; half < 2; half++) {
        long e = half ? e1 : e0;
        const float* ov = o + half * 4;
        __nv_bfloat16 h0, h1, h2, h3, l0, l1, l2, l3;
        split2(ov[0], h0, l0); split2(ov[1], h1, l1);
        split2(ov[2], h2, l2); split2(ov[3], h3, l3);
        __nv_bfloat162 ph0; ph0.x = h0; ph0.y = h1;
        __nv_bfloat162 ph1; ph1.x = h2; ph1.y = h3;
        __nv_bfloat162 pl0; pl0.x = l0; pl0.y = l1;
        __nv_bfloat162 pl1; pl1.x = l2; pl1.y = l3;
        *(__nv_bfloat162*)(g_xrh + e)     = ph0;
        *(__nv_bfloat162*)(g_xrh + e + 2) = ph1;
        *(__nv_bfloat162*)(g_xrl + e)     = pl0;
        *(__nv_bfloat162*)(g_xrl + e + 2) = pl1;
    }
}

// ---------------------------------------------------------------------------
// Flash attention (SIMT). Epilogue emits bf16 hi/lo for TC out-projection.
// ---------------------------------------------------------------------------
__global__ __launch_bounds__(256) void attention_kernel() {
    __shared__ float Qs[32][132];
    __shared__ float Ks[32][36];
    __shared__ float Vs[32][32];
    __shared__ float Ps[32][132];

    int tid = threadIdx.x;
    int tx = tid & 15, ty = tid >> 4;
    int n0 = blockIdx.x * 128;
    int h  = blockIdx.y;
    int b  = blockIdx.z;

    const float* Qg = g_q  + ((long)b * Nn + n0) * Cc + h * 32;
    const float* Kg = g_k2 + (long)b * Mm * Cc + h * 32;
    const float* Vg = g_v1 + (long)b * Mm * Cc + h * 32;
    const float scale = 0.17677669529663689f;

#pragma unroll
    for (int i = 0; i < 4; i++) {
        int id = tid + i * 256;
        int row = id >> 3, c4 = id & 7;
        float4 v = *(const float4*)(Qg + (long)row * Cc + c4 * 4);
        Qs[c4 * 4 + 0][row] = v.x * scale;
        Qs[c4 * 4 + 1][row] = v.y * scale;
        Qs[c4 * 4 + 2][row] = v.z * scale;
        Qs[c4 * 4 + 3][row] = v.w * scale;
    }
    __syncthreads();

    float mrun[8], lrun[8], O[8][2];
#pragma unroll
    for (int i = 0; i < 8; i++) {
        mrun[i] = -1e30f; lrun[i] = 0.f; O[i][0] = 0.f; O[i][1] = 0.f;
    }

    for (int mc = 0; mc < Mm / 32; mc++) {
        {
            int row = tid >> 3, c4 = tid & 7;
            float4 kv = *(const float4*)(Kg + (long)(mc * 32 + row) * Cc + c4 * 4);
            Ks[c4 * 4 + 0][row] = kv.x;
            Ks[c4 * 4 + 1][row] = kv.y;
            Ks[c4 * 4 + 2][row] = kv.z;
            Ks[c4 * 4 + 3][row] = kv.w;
            float4 vv = *(const float4*)(Vg + (long)(mc * 32 + row) * Cc + c4 * 4);
            *(float4*)&Vs[row][c4 * 4] = vv;
        }
        __syncthreads();

        float s[8][2];
#pragma unroll
        for (int i = 0; i < 8; i++) { s[i][0] = 0.f; s[i][1] = 0.f; }
#pragma unroll
        for (int k = 0; k < 32; k++) {
            float4 a0 = *(float4*)&Qs[k][ty * 8];
            float4 a1 = *(float4*)&Qs[k][ty * 8 + 4];
            float k0 = Ks[k][tx * 2], k1 = Ks[k][tx * 2 + 1];
            float a[8] = {a0.x, a0.y, a0.z, a0.w, a1.x, a1.y, a1.z, a1.w};
#pragma unroll
            for (int i = 0; i < 8; i++) {
                s[i][0] = fmaf(a[i], k0, s[i][0]);
                s[i][1] = fmaf(a[i], k1, s[i][1]);
            }
        }

#pragma unroll
        for (int i = 0; i < 8; i++) {
            float mx = fmaxf(s[i][0], s[i][1]);
#pragma unroll
            for (int off = 8; off; off >>= 1)
                mx = fmaxf(mx, __shfl_xor_sync(0xffffffffu, mx, off));
            float mnew = fmaxf(mrun[i], mx);
            float p0 = __expf(s[i][0] - mnew);
            float p1 = __expf(s[i][1] - mnew);
            float alpha = __expf(mrun[i] - mnew);
            mrun[i] = mnew;
            float rs = p0 + p1;
#pragma unroll
            for (int off = 8; off; off >>= 1)
                rs += __shfl_xor_sync(0xffffffffu, rs, off);
            lrun[i] = lrun[i] * alpha + rs;
            O[i][0] *= alpha;
            O[i][1] *= alpha;
            Ps[tx * 2 + 0][ty * 8 + i] = p0;
            Ps[tx * 2 + 1][ty * 8 + i] = p1;
        }
        __syncthreads();

#pragma unroll
        for (int c = 0; c < 32; c++) {
            float4 p0 = *(float4*)&Ps[c][ty * 8];
            float4 p1 = *(float4*)&Ps[c][ty * 8 + 4];
            float v0 = Vs[c][tx * 2], v1 = Vs[c][tx * 2 + 1];
            float p[8] = {p0.x, p0.y, p0.z, p0.w, p1.x, p1.y, p1.z, p1.w};
#pragma unroll
            for (int i = 0; i < 8; i++) {
                O[i][0] = fmaf(p[i], v0, O[i][0]);
                O[i][1] = fmaf(p[i], v1, O[i][1]);
            }
        }
        __syncthreads();
    }

    long base = ((long)b * Nn + n0) * Cc + h * 32;
#pragma unroll
    for (int i = 0; i < 8; i++) {
        float inv = 1.f / lrun[i];
        float ox = O[i][0] * inv, oy = O[i][1] * inv;
        __nv_bfloat16 h0, h1, l0, l1;
        split2(ox, h0, l0);
        split2(oy, h1, l1);
        long e = base + (long)(ty * 8 + i) * Cc + tx * 2;
        __nv_bfloat162 ph; ph.x = h0; ph.y = h1;
        __nv_bfloat162 pl; pl.x = l0; pl.y = l1;
        *(__nv_bfloat162*)(g_ath + e) = ph;
        *(__nv_bfloat162*)(g_atl + e) = pl;
    }
}

// ---------------------------------------------------------------------------
extern "C" void kernel_launch(void* const* d_in, const int* in_sizes, int n_in,
                              void* d_out, int out_size) {
    const float* x1     = (const float*)d_in[0];
    const float* x2     = (const float*)d_in[1];
    const float* q_w    = (const float*)d_in[2];
    const float* kv_w   = (const float*)d_in[3];
    const float* sr_w   = (const float*)d_in[4];
    const float* sr_b   = (const float*)d_in[5];
    const float* ln_g   = (const float*)d_in[6];
    const float* ln_b   = (const float*)d_in[7];
    const float* proj_w = (const float*)d_in[8];
    const float* proj_b = (const float*)d_in[9];
    float* out = (float*)d_out;

    float *p_q, *p_xr, *p_k2, *p_v1;
    cudaGetSymbolAddress((void**)&p_q, g_q);
    cudaGetSymbolAddress((void**)&p_xr, g_xr);
    cudaGetSymbolAddress((void**)&p_k2, g_k2);
    cudaGetSymbolAddress((void**)&p_v1, g_v1);
    __nv_bfloat16 *p_x1h, *p_x1l, *p_gah, *p_gal, *p_srh, *p_srl;
    __nv_bfloat16 *p_xrh, *p_xrl, *p_ath, *p_atl;
    __nv_bfloat16 *p_qwh, *p_qwl, *p_kwh, *p_kwl, *p_pwh, *p_pwl;
    cudaGetSymbolAddress((void**)&p_x1h, g_x1h);
    cudaGetSymbolAddress((void**)&p_x1l, g_x1l);
    cudaGetSymbolAddress((void**)&p_gah, g_gah);
    cudaGetSymbolAddress((void**)&p_gal, g_gal);
    cudaGetSymbolAddress((void**)&p_srh, g_srh);
    cudaGetSymbolAddress((void**)&p_srl, g_srl);
    cudaGetSymbolAddress((void**)&p_xrh, g_xrh);
    cudaGetSymbolAddress((void**)&p_xrl, g_xrl);
    cudaGetSymbolAddress((void**)&p_ath, g_ath);
    cudaGetSymbolAddress((void**)&p_atl, g_atl);
    cudaGetSymbolAddress((void**)&p_qwh, g_qwh);
    cudaGetSymbolAddress((void**)&p_qwl, g_qwl);
    cudaGetSymbolAddress((void**)&p_kwh, g_kwh);
    cudaGetSymbolAddress((void**)&p_kwl, g_kwl);
    cudaGetSymbolAddress((void**)&p_pwh, g_pwh);
    cudaGetSymbolAddress((void**)&p_pwl, g_pwl);

    // 1) weight + input splits
    pack_srw_kernel<<<1024, 256>>>(sr_w);
    gather_kernel<<<4096, 256>>>(x1, x2);
    split_kernel<<<2048, 256>>>(x1, p_x1h, p_x1l, (Bb * Nn * Cc) / 4);
    split_kernel<<<64, 256>>>(q_w, p_qwh, p_qwl, (Cc * Cc) / 4);
    split_kernel<<<128, 256>>>(kv_w, p_kwh, p_kwl, (2 * Cc * Cc) / 4);
    split_kernel<<<64, 256>>>(proj_w, p_pwh, p_pwl, (Cc * Cc) / 4);

    // 2) q = x1 @ q_w^T
    gemm_mma_kernel<<<dim3(64, 4), 256>>>(p_x1h, p_x1l, p_qwh, p_qwl,
                                          nullptr, p_q, Cc, Cc);
    // 3) conv-as-GEMM + bias
    gemm_mma_kernel<<<dim3(32, 4), 256>>>(p_gah, p_gal, p_srh, p_srl,
                                          sr_b, p_xr, Cc, Kc);
    // 4) layernorm -> bf16 splits
    layernorm_kernel<<<512, 256>>>(ln_g, ln_b);
    // 5) k2 = x2r @ kv_w[0:256]^T ; v1 = x1r @ kv_w[256:512]^T
    gemm_mma_kernel<<<dim3(16, 4), 256>>>(
        p_xrh + (long)Bb * Mm * Cc, p_xrl + (long)Bb * Mm * Cc,
        p_kwh, p_kwl, nullptr, p_k2, Cc, Cc);
    gemm_mma_kernel<<<dim3(16, 4), 256>>>(
        p_xrh, p_xrl, p_kwh + Cc * Cc, p_kwl + Cc * Cc,
        nullptr, p_v1, Cc, Cc);
    // 6) flash attention -> bf16 splits
    attention_kernel<<<dim3(Nn / 128, Hh, Bb), 256>>>();
    // 7) out = attn @ proj_w^T + proj_b
    gemm_mma_kernel<<<dim3(64, 4), 256>>>(p_ath, p_atl, p_pwh, p_pwl,
                                          proj_b, out, Cc, Cc);
}

// round 7
// speedup vs baseline: 1.7454x; 1.5143x over previous
#include <cuda_runtime.h>
#include <cuda_bf16.h>
#include <cstdint>
#include <math.h>

// Problem constants
constexpr int Bb = 2;
constexpr int Nn = 4096;
constexpr int Cc = 256;
constexpr int Hh = 8;
constexpr int Mm = 1024;      // reduced tokens (32x32)
constexpr int Kc = 1024;      // conv-as-GEMM K (4 * 256)

// -------- scratch (static device allocations; no cudaMalloc allowed) --------
__device__ float g_xr  [2 * Bb * Mm * Cc];      // fp32 conv output (pre-LN)

__device__ __nv_bfloat16 g_x1h [Bb * Nn * Cc];      // x1 split
__device__ __nv_bfloat16 g_x1l [Bb * Nn * Cc];
__device__ __nv_bfloat16 g_gah [2 * Bb * Mm * Kc];  // gathered patches split
__device__ __nv_bfloat16 g_gal [2 * Bb * Mm * Kc];
__device__ __nv_bfloat16 g_srh [Cc * Kc];           // packed sr_w split
__device__ __nv_bfloat16 g_srl [Cc * Kc];
__device__ __nv_bfloat16 g_xrh [2 * Bb * Mm * Cc];  // post-LN split
__device__ __nv_bfloat16 g_xrl [2 * Bb * Mm * Cc];
__device__ __nv_bfloat16 g_qh  [Bb * Nn * Cc];      // q split (from q GEMM)
__device__ __nv_bfloat16 g_ql  [Bb * Nn * Cc];
__device__ __nv_bfloat16 g_k2h [Bb * Mm * Cc];      // k2 split
__device__ __nv_bfloat16 g_k2l [Bb * Mm * Cc];
__device__ __nv_bfloat16 g_v1h [Bb * Mm * Cc];      // v1 split
__device__ __nv_bfloat16 g_v1l [Bb * Mm * Cc];
__device__ __nv_bfloat16 g_ath [Bb * Nn * Cc];      // attention out split
__device__ __nv_bfloat16 g_atl [Bb * Nn * Cc];
__device__ __nv_bfloat16 g_qwh [Cc * Cc];
__device__ __nv_bfloat16 g_qwl [Cc * Cc];
__device__ __nv_bfloat16 g_kwh [2 * Cc * Cc];
__device__ __nv_bfloat16 g_kwl [2 * Cc * Cc];
__device__ __nv_bfloat16 g_pwh [Cc * Cc];
__device__ __nv_bfloat16 g_pwl [Cc * Cc];

// ---------------------------------------------------------------------------
__device__ __forceinline__ uint32_t smem_u32(const void* p) {
    uint32_t a;
    asm("{ .reg .u64 t; cvta.to.shared.u64 t, %1; cvt.u32.u64 %0, t; }"
        : "=r"(a) : "l"(p));
    return a;
}
__device__ __forceinline__ void split2(float v, __nv_bfloat16& h, __nv_bfloat16& l) {
    h = __float2bfloat16(v);
    l = __float2bfloat16(v - __bfloat162float(h));
}
__device__ __forceinline__ uint32_t pack_split_hi(float a, float b) {
    __nv_bfloat162 p;
    p.x = __float2bfloat16(a);
    p.y = __float2bfloat16(b);
    return *(uint32_t*)&p;
}
__device__ __forceinline__ uint32_t pack_split_lo(float a, float b) {
    __nv_bfloat162 p;
    p.x = __float2bfloat16(a - __bfloat162float(__float2bfloat16(a)));
    p.y = __float2bfloat16(b - __bfloat162float(__float2bfloat16(b)));
    return *(uint32_t*)&p;
}

#define LDSM_X4(r0, r1, r2, r3, addr) \
    asm volatile("ldmatrix.sync.aligned.m8n8.x4.shared.b16 {%0,%1,%2,%3}, [%4];" \
                 : "=r"(r0), "=r"(r1), "=r"(r2), "=r"(r3) : "r"(addr))

#define MMA_BF16(c, a, b) \
    asm volatile("mma.sync.aligned.m16n8k16.row.col.f32.bf16.bf16.f32 " \
                 "{%0,%1,%2,%3}, {%4,%5,%6,%7}, {%8,%9}, {%0,%1,%2,%3};" \
                 : "+f"((c)[0]), "+f"((c)[1]), "+f"((c)[2]), "+f"((c)[3]) \
                 : "r"((a)[0]), "r"((a)[1]), "r"((a)[2]), "r"((a)[3]), \
                   "r"((b)[0]), "r"((b)[1]))

// ---------------------------------------------------------------------------
// Pack sr_w [co][ci][kh][kw] -> hi/lo bf16 [co][ seg*256 + ci ]
// ---------------------------------------------------------------------------
__global__ void pack_srw_kernel(const float* __restrict__ srw) {
    int idx = blockIdx.x * 256 + threadIdx.x;
    int co = idx >> 10;
    int k  = idx & 1023;
    int seg = k >> 8;
    int ci  = k & 255;
    float v = srw[((co << 8) + ci) * 4 + seg];
    __nv_bfloat16 h, l;
    split2(v, h, l);
    g_srh[idx] = h;
    g_srl[idx] = l;
}

// ---------------------------------------------------------------------------
// Gather conv patches -> hi/lo bf16
// ---------------------------------------------------------------------------
__global__ void gather_kernel(const float* __restrict__ x1,
                              const float* __restrict__ x2) {
    unsigned idx = blockIdx.x * 256 + threadIdx.x;   // float4 index, 2^20 total
    int k4  = idx & 255;
    int m   = (idx >> 8) & 1023;
    int b   = (idx >> 18) & 1;
    int src = (idx >> 19) & 1;
    int seg = k4 >> 6;
    int ci4 = k4 & 63;
    int i = m >> 5, j = m & 31;
    int kh = seg >> 1, kw = seg & 1;
    int n = (2 * i + kh) * 64 + 2 * j + kw;
    const float* sp = src ? x2 : x1;
    float4 v = *(const float4*)(sp + ((long)b * Nn + n) * Cc + ci4 * 4);
    uint32_t ph0 = pack_split_hi(v.x, v.y), ph1 = pack_split_hi(v.z, v.w);
    uint32_t pl0 = pack_split_lo(v.x, v.y), pl1 = pack_split_lo(v.z, v.w);
    ((uint32_t*)g_gah)[idx * 2]     = ph0;
    ((uint32_t*)g_gah)[idx * 2 + 1] = ph1;
    ((uint32_t*)g_gal)[idx * 2]     = pl0;
    ((uint32_t*)g_gal)[idx * 2 + 1] = pl1;
}

// ---------------------------------------------------------------------------
// Generic fp32 -> (hi,lo) bf16 split, float4 vectorized. n4 = n/4 float4s.
// ---------------------------------------------------------------------------
__global__ void split_kernel(const float* __restrict__ in,
                             __nv_bfloat16* __restrict__ oh,
                             __nv_bfloat16* __restrict__ ol, int n4) {
    int idx = blockIdx.x * 256 + threadIdx.x;
    if (idx >= n4) return;
    float4 v = ((const float4*)in)[idx];
    ((uint32_t*)oh)[idx * 2]     = pack_split_hi(v.x, v.y);
    ((uint32_t*)oh)[idx * 2 + 1] = pack_split_hi(v.z, v.w);
    ((uint32_t*)ol)[idx * 2]     = pack_split_lo(v.x, v.y);
    ((uint32_t*)ol)[idx * 2 + 1] = pack_split_lo(v.z, v.w);
}

// ---------------------------------------------------------------------------
// mma.sync GEMM, bf16x2 split emulation of fp32.  (validated in Round 3)
// ---------------------------------------------------------------------------
constexpr int AST = 40;   // smem stride in halves (80B rows)

template <bool SPLIT>
__global__ __launch_bounds__(256) void gemm_mma_kernel(
    const __nv_bfloat16* __restrict__ Ah, const __nv_bfloat16* __restrict__ Al,
    const __nv_bfloat16* __restrict__ Wh, const __nv_bfloat16* __restrict__ Wl,
    const float* __restrict__ bias, float* __restrict__ Cout,
    __nv_bfloat16* __restrict__ Ch, __nv_bfloat16* __restrict__ Cl,
    int Ndim, int K)
{
    __shared__ __nv_bfloat16 sAh[128 * AST], sAl[128 * AST];
    __shared__ __nv_bfloat16 sWh[64 * AST],  sWl[64 * AST];
    __shared__ float sbias[64];

    int tid = threadIdx.x, lane = tid & 31, wid = tid >> 5;
    int wm = wid >> 1, wn = wid & 1;
    int m0 = blockIdx.x * 128, n0 = blockIdx.y * 64;

    if (tid < 64) sbias[tid] = bias ? bias[n0 + tid] : 0.f;

    float acc[2][4][4];
#pragma unroll
    for (int mt = 0; mt < 2; mt++)
#pragma unroll
        for (int nt = 0; nt < 4; nt++)
#pragma unroll
            for (int e = 0; e < 4; e++) acc[mt][nt][e] = 0.f;

    int a_row  = wm * 32 + (lane & 15);
    int a_colb = (lane >> 4) << 3;
    int b_row  = wn * 32 + ((lane >> 4) << 3) + (lane & 7);
    int b_colb = ((lane >> 3) & 1) << 3;

    uint32_t sa_h = smem_u32(sAh), sa_l = smem_u32(sAl);
    uint32_t sb_h = smem_u32(sWh), sb_l = smem_u32(sWl);

    int ar = tid >> 1, ahalf = tid & 1;
    int brr = tid >> 2, bq = tid & 3;

    for (int k0 = 0; k0 < K; k0 += 32) {
        {
            size_t ga = (size_t)(m0 + ar) * K + k0 + ahalf * 16;
            const uint4* pAh = (const uint4*)(Ah + ga);
            const uint4* pAl = (const uint4*)(Al + ga);
            *(uint4*)&sAh[ar * AST + ahalf * 16]     = pAh[0];
            *(uint4*)&sAh[ar * AST + ahalf * 16 + 8] = pAh[1];
            *(uint4*)&sAl[ar * AST + ahalf * 16]     = pAl[0];
            *(uint4*)&sAl[ar * AST + ahalf * 16 + 8] = pAl[1];
            size_t gb = (size_t)(n0 + brr) * K + k0 + bq * 8;
            *(uint4*)&sWh[brr * AST + bq * 8] = *(const uint4*)(Wh + gb);
            *(uint4*)&sWl[brr * AST + bq * 8] = *(const uint4*)(Wl + gb);
        }
        __syncthreads();

#pragma unroll
        for (int ks = 0; ks < 32; ks += 16) {
            uint32_t aH[2][4], aL[2][4], bH[4][2], bL[4][2];
#pragma unroll
            for (int mt = 0; mt < 2; mt++) {
                uint32_t off = (uint32_t)(((a_row + mt * 16) * AST + ks + a_colb) * 2);
                LDSM_X4(aH[mt][0], aH[mt][1], aH[mt][2], aH[mt][3], sa_h + off);
                LDSM_X4(aL[mt][0], aL[mt][1], aL[mt][2], aL[mt][3], sa_l + off);
            }
#pragma unroll
            for (int p = 0; p < 2; p++) {
                uint32_t off = (uint32_t)(((b_row + p * 16) * AST + ks + b_colb) * 2);
                uint32_t r0, r1, r2, r3;
                LDSM_X4(r0, r1, r2, r3, sb_h + off);
                bH[p * 2][0] = r0; bH[p * 2][1] = r1;
                bH[p * 2 + 1][0] = r2; bH[p * 2 + 1][1] = r3;
                LDSM_X4(r0, r1, r2, r3, sb_l + off);
                bL[p * 2][0] = r0; bL[p * 2][1] = r1;
                bL[p * 2 + 1][0] = r2; bL[p * 2 + 1][1] = r3;
            }
#pragma unroll
            for (int mt = 0; mt < 2; mt++)
#pragma unroll
                for (int nt = 0; nt < 4; nt++) {
                    MMA_BF16(acc[mt][nt], aH[mt], bH[nt]);
                    MMA_BF16(acc[mt][nt], aH[mt], bL[nt]);
                    MMA_BF16(acc[mt][nt], aL[mt], bH[nt]);
                }
        }
        __syncthreads();
    }

    int g = lane >> 2, tig = lane & 3;
#pragma unroll
    for (int mt = 0; mt < 2; mt++)
#pragma unroll
        for (int hf = 0; hf < 2; hf++) {
            int row = m0 + wm * 32 + mt * 16 + g + hf * 8;
#pragma unroll
            for (int nt = 0; nt < 4; nt++) {
                int cb = wn * 32 + nt * 8 + tig * 2;
                float ox = acc[mt][nt][hf * 2 + 0] + sbias[cb];
                float oy = acc[mt][nt][hf * 2 + 1] + sbias[cb + 1];
                size_t e = (size_t)row * Ndim + n0 + cb;
                if (SPLIT) {
                    *(uint32_t*)(Ch + e) = pack_split_hi(ox, oy);
                    *(uint32_t*)(Cl + e) = pack_split_lo(ox, oy);
                } else {
                    float2 o; o.x = ox; o.y = oy;
                    *(float2*)(Cout + e) = o;
                }
            }
        }
}

// ---------------------------------------------------------------------------
// LayerNorm over rows of g_xr (4096 x 256); writes bf16 hi/lo splits.
// ---------------------------------------------------------------------------
__global__ __launch_bounds__(256) void layernorm_kernel(
    const float* __restrict__ g, const float* __restrict__ b)
{
    int warp = threadIdx.x >> 5, lane = threadIdx.x & 31;
    long row = (long)blockIdx.x * 8 + warp;
    const float* p = g_xr + row * 256;

    float4 v0 = ((const float4*)p)[lane];
    float4 v1 = ((const float4*)p)[lane + 32];
    float s  = v0.x + v0.y + v0.z + v0.w + v1.x + v1.y + v1.z + v1.w;
    float sq = v0.x * v0.x + v0.y * v0.y + v0.z * v0.z + v0.w * v0.w +
               v1.x * v1.x + v1.y * v1.y + v1.z * v1.z + v1.w * v1.w;
#pragma unroll
    for (int off = 16; off; off >>= 1) {
        s  += __shfl_xor_sync(0xffffffffu, s, off);
        sq += __shfl_xor_sync(0xffffffffu, sq, off);
    }
    float mu = s * (1.f / 256.f);
    float var = sq * (1.f / 256.f) - mu * mu;
    float rs = rsqrtf(var + 1e-5f);

    float4 g0 = ((const float4*)g)[lane];
    float4 b0 = ((const float4*)b)[lane];
    float4 g1 = ((const float4*)g)[lane + 32];
    float4 b1 = ((const float4*)b)[lane + 32];
    float o[8];
    o[0] = (v0.x - mu) * rs * g0.x + b0.x;
    o[1] = (v0.y - mu) * rs * g0.y + b0.y;
    o[2] = (v0.z - mu) * rs * g0.z + b0.z;
    o[3] = (v0.w - mu) * rs * g0.w + b0.w;
    o[4] = (v1.x - mu) * rs * g1.x + b1.x;
    o[5] = (v1.y - mu) * rs * g1.y + b1.y;
    o[6] = (v1.z - mu) * rs * g1.z + b1.z;
    o[7] = (v1.w - mu) * rs * g1.w + b1.w;

    long e0 = row * 256 + lane * 4;
    long e1 = row * 256 + (lane + 32) * 4;
#pragma unroll
    for (int half = 0; half < 2; half++) {
        long e = half ? e1 : e0;
        const float* ov = o + half * 4;
        *(uint32_t*)(g_xrh + e)     = pack_split_hi(ov[0], ov[1]);
        *(uint32_t*)(g_xrh + e + 2) = pack_split_hi(ov[2], ov[3]);
        *(uint32_t*)(g_xrl + e)     = pack_split_lo(ov[0], ov[1]);
        *(uint32_t*)(g_xrl + e + 2) = pack_split_lo(ov[2], ov[3]);
    }
}

// ---------------------------------------------------------------------------
// Flash attention v2: MMA for QK^T and P.V using the Round-3-validated
// ldmatrix patterns; softmax in SIMT via an smem round trip.
// CTA = 128 q-rows x one (b,h); 8 warps; 32 key-chunks of 32.
// FIX (R7): Q and K smem loads now cover all 32 columns (two uint4 per
// thread, matching the validated GEMM A-loader). R5/R6 left cols 16..31
// uninitialized -> NaN.
// ---------------------------------------------------------------------------
constexpr int O_QH  = 0;                 // 128x40 bf16
constexpr int O_QL  = O_QH  + 10240;
constexpr int O_KH  = O_QL  + 10240;     // 32x40 bf16
constexpr int O_KL  = O_KH  + 2560;
constexpr int O_VTH = O_KL  + 2560;      // 32x40 bf16, V transposed [d][key]
constexpr int O_VTL = O_VTH + 2560;
constexpr int O_SS  = O_VTL + 2560;      // 128x34 fp32
constexpr int O_PH  = O_SS  + 17408;     // 128x40 bf16
constexpr int O_PL  = O_PH  + 10240;
constexpr int O_ALF = O_PL  + 10240;     // 128 fp32
constexpr int O_LIV = O_ALF + 512;       // 128 fp32
constexpr int ATT_SMEM = O_LIV + 512;    // 69632

__global__ __launch_bounds__(256) void attention_mma2_kernel() {
    extern __shared__ char sm[];
    __nv_bfloat16* sQh  = (__nv_bfloat16*)(sm + O_QH);
    __nv_bfloat16* sQl  = (__nv_bfloat16*)(sm + O_QL);
    __nv_bfloat16* sKh  = (__nv_bfloat16*)(sm + O_KH);
    __nv_bfloat16* sKl  = (__nv_bfloat16*)(sm + O_KL);
    __nv_bfloat16* sVth = (__nv_bfloat16*)(sm + O_VTH);
    __nv_bfloat16* sVtl = (__nv_bfloat16*)(sm + O_VTL);
    float* sS  = (float*)(sm + O_SS);
    __nv_bfloat16* sPh = (__nv_bfloat16*)(sm + O_PH);
    __nv_bfloat16* sPl = (__nv_bfloat16*)(sm + O_PL);
    float* sAlf = (float*)(sm + O_ALF);
    float* sLiv = (float*)(sm + O_LIV);

    int tid = threadIdx.x, lane = tid & 31, wid = tid >> 5;
    int n0 = blockIdx.x * 128, h = blockIdx.y, b = blockIdx.z;
    int g = lane >> 2, tig = lane & 3;
    const float scale = 0.17677669529663689f;   // 1/sqrt(32)

    const __nv_bfloat16* QhG = g_qh  + ((long)b * Nn + n0) * Cc + h * 32;
    const __nv_bfloat16* QlG = g_ql  + ((long)b * Nn + n0) * Cc + h * 32;
    const __nv_bfloat16* KhG = g_k2h + (long)b * Mm * Cc + h * 32;
    const __nv_bfloat16* KlG = g_k2l + (long)b * Mm * Cc + h * 32;
    const __nv_bfloat16* VhG = g_v1h + (long)b * Mm * Cc + h * 32;
    const __nv_bfloat16* VlG = g_v1l + (long)b * Mm * Cc + h * 32;

    // Load Q tile (128 x 32) hi/lo into smem — full 32 cols per row (FIXED)
    {
        int r = tid >> 1, hf = tid & 1;
        const __nv_bfloat16* qs = QhG + (long)r * Cc + hf * 16;
        *(uint4*)&sQh[r * AST + hf * 16]     = *(const uint4*)(qs);
        *(uint4*)&sQh[r * AST + hf * 16 + 8] = *(const uint4*)(qs + 8);
        const __nv_bfloat16* qsl = QlG + (long)r * Cc + hf * 16;
        *(uint4*)&sQl[r * AST + hf * 16]     = *(const uint4*)(qsl);
        *(uint4*)&sQl[r * AST + hf * 16 + 8] = *(const uint4*)(qsl + 8);
    }
    __syncthreads();

    // Persistent Q a-frags (validated A pattern)
    uint32_t qh[2][4], ql[2][4];
    {
        int a_row = wid * 16 + (lane & 15);
        int a_colb = (lane >> 4) << 3;
        uint32_t sq_h = smem_u32(sQh), sq_l = smem_u32(sQl);
#pragma unroll
        for (int ks = 0; ks < 2; ks++) {
            uint32_t off = (uint32_t)((a_row * AST + ks * 16 + a_colb) * 2);
            LDSM_X4(qh[ks][0], qh[ks][1], qh[ks][2], qh[ks][3], sq_h + off);
            LDSM_X4(ql[ks][0], ql[ks][1], ql[ks][2], ql[ks][3], sq_l + off);
        }
    }

    // Softmax role: thread t owns row sr = t>>1, key-half shf = t&1 (16 keys)
    int sr = tid >> 1, shf = tid & 1;
    float mrun = -1e30f, lrun = 0.f;

    float O[4][4];
#pragma unroll
    for (int dt = 0; dt < 4; dt++)
#pragma unroll
        for (int e = 0; e < 4; e++) O[dt][e] = 0.f;

    uint32_t sk_h = smem_u32(sKh), sk_l = smem_u32(sKl);
    uint32_t sp_h = smem_u32(sPh), sp_l = smem_u32(sPl);
    uint32_t sv_h = smem_u32(sVth), sv_l = smem_u32(sVtl);

    // validated B-pattern addressing (same formula as GEMM W path)
    int b_row  = ((lane >> 4) << 3) + (lane & 7);
    int b_colb = ((lane >> 3) & 1) << 3;
    // validated A-pattern addressing for P
    int pa_row  = wid * 16 + (lane & 15);
    int pa_colb = (lane >> 4) << 3;

    for (int mc = 0; mc < Mm / 32; mc++) {
        __syncthreads();   // S1: prior chunk's smem reads complete

        // ---- load K (full 32 cols per row — FIXED) ----
        if (tid < 128) {
            int buf = tid >> 6;            // 0: hi, 1: lo
            int i = tid & 63, r = i >> 1, hf = i & 1;
            const __nv_bfloat16* src = (buf ? KlG : KhG)
                + (long)(mc * 32 + r) * Cc + hf * 16;
            __nv_bfloat16* dst = buf ? sKl : sKh;
            *(uint4*)&dst[r * AST + hf * 16]     = *(const uint4*)(src);
            *(uint4*)&dst[r * AST + hf * 16 + 8] = *(const uint4*)(src + 8);
        }
        // ---- load V transposed to [d][key] (covers all 32 d-cols) ----
        {
            int buf = tid >> 7;            // 0: hi, 1: lo
            int i = tid & 127, k = i & 31, dg = i >> 5;   // dg: d block of 8
            const __nv_bfloat16* src = buf ? VlG : VhG;
            __nv_bfloat16* dst = buf ? sVtl : sVth;
            uint4 v = *(const uint4*)(src + (long)(mc * 32 + k) * Cc + dg * 8);
            const __nv_bfloat16* hv = (const __nv_bfloat16*)&v;
#pragma unroll
            for (int j = 0; j < 8; j++)
                dst[(dg * 8 + j) * AST + k] = hv[j];
        }
        __syncthreads();   // S2

        // ---- S = Q @ K^T (3-pass split; validated patterns) ----
        float s[4][4];
#pragma unroll
        for (int nt = 0; nt < 4; nt++)
#pragma unroll
            for (int e = 0; e < 4; e++) s[nt][e] = 0.f;

#pragma unroll
        for (int ks = 0; ks < 2; ks++) {
            uint32_t kh[4][2], kl[4][2];
#pragma unroll
            for (int grp = 0; grp < 2; grp++) {
                uint32_t off = (uint32_t)(((grp * 16 + b_row) * AST + ks * 16 + b_colb) * 2);
                uint32_t r0, r1, r2, r3;
                LDSM_X4(r0, r1, r2, r3, sk_h + off);
                kh[grp * 2][0] = r0; kh[grp * 2][1] = r1;
                kh[grp * 2 + 1][0] = r2; kh[grp * 2 + 1][1] = r3;
                LDSM_X4(r0, r1, r2, r3, sk_l + off);
                kl[grp * 2][0] = r0; kl[grp * 2][1] = r1;
                kl[grp * 2 + 1][0] = r2; kl[grp * 2 + 1][1] = r3;
            }
#pragma unroll
            for (int nt = 0; nt < 4; nt++) {
                MMA_BF16(s[nt], qh[ks], kh[nt]);
                MMA_BF16(s[nt], qh[ks], kl[nt]);
                MMA_BF16(s[nt], ql[ks], kh[nt]);
            }
        }

        // ---- store scaled S to smem ----
#pragma unroll
        for (int nt = 0; nt < 4; nt++) {
            float2 a; a.x = s[nt][0] * scale; a.y = s[nt][1] * scale;
            float2 c; c.x = s[nt][2] * scale; c.y = s[nt][3] * scale;
            *(float2*)&sS[(wid * 16 + g) * 34 + nt * 8 + tig * 2]     = a;
            *(float2*)&sS[(wid * 16 + g + 8) * 34 + nt * 8 + tig * 2] = c;
        }
        __syncthreads();   // S3

        // ---- SIMT online softmax ----
        {
            float sv[16];
#pragma unroll
            for (int j2 = 0; j2 < 8; j2++) {
                float2 t2 = *(float2*)&sS[sr * 34 + shf * 16 + j2 * 2];
                sv[j2 * 2] = t2.x; sv[j2 * 2 + 1] = t2.y;
            }
            float mx = sv[0];
#pragma unroll
            for (int j = 1; j < 16; j++) mx = fmaxf(mx, sv[j]);
            mx = fmaxf(mx, __shfl_xor_sync(0xffffffffu, mx, 1));
            float mnew = fmaxf(mrun, mx);
            float alpha = __expf(mrun - mnew);
            mrun = mnew;
            float sum = 0.f;
            float pv[16];
#pragma unroll
            for (int j = 0; j < 16; j++) {
                pv[j] = __expf(sv[j] - mnew);
                sum += pv[j];
            }
            sum += __shfl_xor_sync(0xffffffffu, sum, 1);
            lrun = lrun * alpha + sum;
            if (shf == 0) sAlf[sr] = alpha;
#pragma unroll
            for (int j2 = 0; j2 < 8; j2++) {
                int col = shf * 16 + j2 * 2;
                *(uint32_t*)&sPh[sr * AST + col] = pack_split_hi(pv[j2 * 2], pv[j2 * 2 + 1]);
                *(uint32_t*)&sPl[sr * AST + col] = pack_split_lo(pv[j2 * 2], pv[j2 * 2 + 1]);
            }
        }
        __syncthreads();   // S4

        // ---- rescale O by alpha(row) ----
        {
            float a0 = sAlf[wid * 16 + g];
            float a1 = sAlf[wid * 16 + g + 8];
#pragma unroll
            for (int dt = 0; dt < 4; dt++) {
                O[dt][0] *= a0; O[dt][1] *= a0;
                O[dt][2] *= a1; O[dt][3] *= a1;
            }
        }

        // ---- O += P @ Vt (3-pass split; validated A and W patterns) ----
#pragma unroll
        for (int ks = 0; ks < 2; ks++) {
            uint32_t ph[4], pl[4];
            {
                uint32_t off = (uint32_t)((pa_row * AST + ks * 16 + pa_colb) * 2);
                LDSM_X4(ph[0], ph[1], ph[2], ph[3], sp_h + off);
                LDSM_X4(pl[0], pl[1], pl[2], pl[3], sp_l + off);
            }
            uint32_t vh[4][2], vl[4][2];
#pragma unroll
            for (int dblk = 0; dblk < 2; dblk++) {
                uint32_t off = (uint32_t)(((dblk * 16 + b_row) * AST + ks * 16 + b_colb) * 2);
                uint32_t r0, r1, r2, r3;
                LDSM_X4(r0, r1, r2, r3, sv_h + off);
                vh[dblk * 2][0] = r0; vh[dblk * 2][1] = r1;
                vh[dblk * 2 + 1][0] = r2; vh[dblk * 2 + 1][1] = r3;
                LDSM_X4(r0, r1, r2, r3, sv_l + off);
                vl[dblk * 2][0] = r0; vl[dblk * 2][1] = r1;
                vl[dblk * 2 + 1][0] = r2; vl[dblk * 2 + 1][1] = r3;
            }
#pragma unroll
            for (int dt = 0; dt < 4; dt++) {
                MMA_BF16(O[dt], ph, vh[dt]);
                MMA_BF16(O[dt], ph, vl[dt]);
                MMA_BF16(O[dt], pl, vh[dt]);
            }
        }
    }

    // ---- publish 1/l, then epilogue ----
    if (shf == 0) sLiv[sr] = 1.f / lrun;
    __syncthreads();

    long base = ((long)b * Nn + n0) * Cc + h * 32;
    float i0 = sLiv[wid * 16 + g];
    float i1 = sLiv[wid * 16 + g + 8];
#pragma unroll
    for (int rh = 0; rh < 2; rh++) {
        float inv = rh ? i1 : i0;
        int row = wid * 16 + g + rh * 8;
#pragma unroll
        for (int dt = 0; dt < 4; dt++) {
            float ox = O[dt][rh * 2] * inv;
            float oy = O[dt][rh * 2 + 1] * inv;
            long e = base + (long)row * Cc + dt * 8 + tig * 2;
            *(uint32_t*)(g_ath + e) = pack_split_hi(ox, oy);
            *(uint32_t*)(g_atl + e) = pack_split_lo(ox, oy);
        }
    }
}

// ---------------------------------------------------------------------------
extern "C" void kernel_launch(void* const* d_in, const int* in_sizes, int n_in,
                              void* d_out, int out_size) {
    const float* x1     = (const float*)d_in[0];
    const float* x2     = (const float*)d_in[1];
    const float* q_w    = (const float*)d_in[2];
    const float* kv_w   = (const float*)d_in[3];
    const float* sr_w   = (const float*)d_in[4];
    const float* sr_b   = (const float*)d_in[5];
    const float* ln_g   = (const float*)d_in[6];
    const float* ln_b   = (const float*)d_in[7];
    const float* proj_w = (const float*)d_in[8];
    const float* proj_b = (const float*)d_in[9];
    float* out = (float*)d_out;

    cudaFuncSetAttribute(attention_mma2_kernel,
                         cudaFuncAttributeMaxDynamicSharedMemorySize, ATT_SMEM);

    float* p_xr;
    cudaGetSymbolAddress((void**)&p_xr, g_xr);
    __nv_bfloat16 *p_x1h, *p_x1l, *p_gah, *p_gal, *p_srh, *p_srl;
    __nv_bfloat16 *p_xrh, *p_xrl, *p_ath, *p_atl;
    __nv_bfloat16 *p_qh, *p_ql, *p_k2h, *p_k2l, *p_v1h, *p_v1l;
    __nv_bfloat16 *p_qwh, *p_qwl, *p_kwh, *p_kwl, *p_pwh, *p_pwl;
    cudaGetSymbolAddress((void**)&p_x1h, g_x1h);
    cudaGetSymbolAddress((void**)&p_x1l, g_x1l);
    cudaGetSymbolAddress((void**)&p_gah, g_gah);
    cudaGetSymbolAddress((void**)&p_gal, g_gal);
    cudaGetSymbolAddress((void**)&p_srh, g_srh);
    cudaGetSymbolAddress((void**)&p_srl, g_srl);
    cudaGetSymbolAddress((void**)&p_xrh, g_xrh);
    cudaGetSymbolAddress((void**)&p_xrl, g_xrl);
    cudaGetSymbolAddress((void**)&p_ath, g_ath);
    cudaGetSymbolAddress((void**)&p_atl, g_atl);
    cudaGetSymbolAddress((void**)&p_qh, g_qh);
    cudaGetSymbolAddress((void**)&p_ql, g_ql);
    cudaGetSymbolAddress((void**)&p_k2h, g_k2h);
    cudaGetSymbolAddress((void**)&p_k2l, g_k2l);
    cudaGetSymbolAddress((void**)&p_v1h, g_v1h);
    cudaGetSymbolAddress((void**)&p_v1l, g_v1l);
    cudaGetSymbolAddress((void**)&p_qwh, g_qwh);
    cudaGetSymbolAddress((void**)&p_qwl, g_qwl);
    cudaGetSymbolAddress((void**)&p_kwh, g_kwh);
    cudaGetSymbolAddress((void**)&p_kwl, g_kwl);
    cudaGetSymbolAddress((void**)&p_pwh, g_pwh);
    cudaGetSymbolAddress((void**)&p_pwl, g_pwl);

    // 1) weight + input splits
    pack_srw_kernel<<<1024, 256>>>(sr_w);
    gather_kernel<<<4096, 256>>>(x1, x2);
    split_kernel<<<2048, 256>>>(x1, p_x1h, p_x1l, (Bb * Nn * Cc) / 4);
    split_kernel<<<64, 256>>>(q_w, p_qwh, p_qwl, (Cc * Cc) / 4);
    split_kernel<<<128, 256>>>(kv_w, p_kwh, p_kwl, (2 * Cc * Cc) / 4);
    split_kernel<<<64, 256>>>(proj_w, p_pwh, p_pwl, (Cc * Cc) / 4);

    // 2) q = x1 @ q_w^T  -> bf16 hi/lo
    gemm_mma_kernel<true><<<dim3(64, 4), 256>>>(
        p_x1h, p_x1l, p_qwh, p_qwl, nullptr, nullptr, p_qh, p_ql, Cc, Cc);
    // 3) conv-as-GEMM + bias -> fp32 (pre-LN)
    gemm_mma_kernel<false><<<dim3(32, 4), 256>>>(
        p_gah, p_gal, p_srh, p_srl, sr_b, p_xr, nullptr, nullptr, Cc, Kc);
    // 4) layernorm -> bf16 splits
    layernorm_kernel<<<512, 256>>>(ln_g, ln_b);
    // 5) k2 = x2r @ kv_w[0:256]^T ; v1 = x1r @ kv_w[256:512]^T  -> bf16 hi/lo
    gemm_mma_kernel<true><<<dim3(16, 4), 256>>>(
        p_xrh + (long)Bb * Mm * Cc, p_xrl + (long)Bb * Mm * Cc,
        p_kwh, p_kwl, nullptr, nullptr, p_k2h, p_k2l, Cc, Cc);
    gemm_mma_kernel<true><<<dim3(16, 4), 256>>>(
        p_xrh, p_xrl, p_kwh + Cc * Cc, p_kwl + Cc * Cc,
        nullptr, nullptr, p_v1h, p_v1l, Cc, Cc);
    // 6) flash attention v2 (MMA + SIMT softmax) -> bf16 splits
    attention_mma2_kernel<<<dim3(Nn / 128, Hh, Bb), 256, ATT_SMEM>>>();
    // 7) out = attn @ proj_w^T + proj_b
    gemm_mma_kernel<false><<<dim3(64, 4), 256>>>(
        p_ath, p_atl, p_pwh, p_pwl, proj_b, out, nullptr, nullptr, Cc, Cc);
}

// round 8
// speedup vs baseline: 2.2671x; 1.2989x over previous
#include <cuda_runtime.h>
#include <cuda_bf16.h>
#include <cstdint>
#include <math.h>

// Problem constants
constexpr int Bb = 2;
constexpr int Nn = 4096;
constexpr int Cc = 256;
constexpr int Hh = 8;
constexpr int Mm = 1024;      // reduced tokens (32x32)
constexpr int Kc = 1024;      // conv-as-GEMM K (4 * 256)
constexpr long BMC = (long)Bb * Mm * Cc;

// -------- scratch (static device allocations; no cudaMalloc allowed) --------
__device__ float g_xr  [2 * Bb * Mm * Cc];      // fp32 conv output (pre-LN)

__device__ __nv_bfloat16 g_x1h [Bb * Nn * Cc];      // x1 split
__device__ __nv_bfloat16 g_x1l [Bb * Nn * Cc];
__device__ __nv_bfloat16 g_gah [2 * Bb * Mm * Kc];  // gathered patches split
__device__ __nv_bfloat16 g_gal [2 * Bb * Mm * Kc];
__device__ __nv_bfloat16 g_srh [Cc * Kc];           // packed sr_w split
__device__ __nv_bfloat16 g_srl [Cc * Kc];
__device__ __nv_bfloat16 g_xrh [2 * Bb * Mm * Cc];  // post-LN split
__device__ __nv_bfloat16 g_xrl [2 * Bb * Mm * Cc];
__device__ __nv_bfloat16 g_qh  [Bb * Nn * Cc];      // q split (from q GEMM)
__device__ __nv_bfloat16 g_ql  [Bb * Nn * Cc];
__device__ __nv_bfloat16 g_kvh [2 * Bb * Mm * Cc];  // [0]: k2, [1]: v1  (hi)
__device__ __nv_bfloat16 g_kvl [2 * Bb * Mm * Cc];  // (lo)
__device__ __nv_bfloat16 g_ath [Bb * Nn * Cc];      // attention out split
__device__ __nv_bfloat16 g_atl [Bb * Nn * Cc];
__device__ __nv_bfloat16 g_qwh [Cc * Cc];
__device__ __nv_bfloat16 g_qwl [Cc * Cc];
__device__ __nv_bfloat16 g_kwh [2 * Cc * Cc];
__device__ __nv_bfloat16 g_kwl [2 * Cc * Cc];
__device__ __nv_bfloat16 g_pwh [Cc * Cc];
__device__ __nv_bfloat16 g_pwl [Cc * Cc];

// ---------------------------------------------------------------------------
__device__ __forceinline__ uint32_t smem_u32(const void* p) {
    uint32_t a;
    asm("{ .reg .u64 t; cvta.to.shared.u64 t, %1; cvt.u32.u64 %0, t; }"
        : "=r"(a) : "l"(p));
    return a;
}
__device__ __forceinline__ void split2(float v, __nv_bfloat16& h, __nv_bfloat16& l) {
    h = __float2bfloat16(v);
    l = __float2bfloat16(v - __bfloat162float(h));
}
__device__ __forceinline__ uint32_t pack_split_hi(float a, float b) {
    __nv_bfloat162 p;
    p.x = __float2bfloat16(a);
    p.y = __float2bfloat16(b);
    return *(uint32_t*)&p;
}
__device__ __forceinline__ uint32_t pack_split_lo(float a, float b) {
    __nv_bfloat162 p;
    p.x = __float2bfloat16(a - __bfloat162float(__float2bfloat16(a)));
    p.y = __float2bfloat16(b - __bfloat162float(__float2bfloat16(b)));
    return *(uint32_t*)&p;
}
__device__ __forceinline__ void split4_at(const float* __restrict__ in,
                                          __nv_bfloat16* __restrict__ oh,
                                          __nv_bfloat16* __restrict__ ol, int idx) {
    float4 v = ((const float4*)in)[idx];
    ((uint32_t*)oh)[idx * 2]     = pack_split_hi(v.x, v.y);
    ((uint32_t*)oh)[idx * 2 + 1] = pack_split_hi(v.z, v.w);
    ((uint32_t*)ol)[idx * 2]     = pack_split_lo(v.x, v.y);
    ((uint32_t*)ol)[idx * 2 + 1] = pack_split_lo(v.z, v.w);
}

#define LDSM_X4(r0, r1, r2, r3, addr) \
    asm volatile("ldmatrix.sync.aligned.m8n8.x4.shared.b16 {%0,%1,%2,%3}, [%4];" \
                 : "=r"(r0), "=r"(r1), "=r"(r2), "=r"(r3) : "r"(addr))

#define MMA_BF16(c, a, b) \
    asm volatile("mma.sync.aligned.m16n8k16.row.col.f32.bf16.bf16.f32 " \
                 "{%0,%1,%2,%3}, {%4,%5,%6,%7}, {%8,%9}, {%0,%1,%2,%3};" \
                 : "+f"((c)[0]), "+f"((c)[1]), "+f"((c)[2]), "+f"((c)[3]) \
                 : "r"((a)[0]), "r"((a)[1]), "r"((a)[2]), "r"((a)[3]), \
                   "r"((b)[0]), "r"((b)[1]))

// ---------------------------------------------------------------------------
// Fused weight prep: pack+split sr_w, split q_w / kv_w / proj_w.
// Grid 1280 x 256.
// ---------------------------------------------------------------------------
__global__ void prep_weights_kernel(const float* __restrict__ srw,
                                    const float* __restrict__ qw,
                                    const float* __restrict__ kvw,
                                    const float* __restrict__ pw) {
    int bx = blockIdx.x, t = threadIdx.x;
    if (bx < 1024) {                       // pack sr_w (scalar, 256K elems)
        int idx = bx * 256 + t;
        int co = idx >> 10;
        int k  = idx & 1023;
        int seg = k >> 8;
        int ci  = k & 255;
        float v = srw[((co << 8) + ci) * 4 + seg];
        __nv_bfloat16 h, l;
        split2(v, h, l);
        g_srh[idx] = h;
        g_srl[idx] = l;
    } else if (bx < 1088) {                // q_w split (64 blocks, 16384 f4)
        split4_at(qw, g_qwh, g_qwl, (bx - 1024) * 256 + t);
    } else if (bx < 1216) {                // kv_w split (128 blocks)
        split4_at(kvw, g_kwh, g_kwl, (bx - 1088) * 256 + t);
    } else {                               // proj_w split (64 blocks)
        split4_at(pw, g_pwh, g_pwl, (bx - 1216) * 256 + t);
    }
}

// ---------------------------------------------------------------------------
// Fused input prep: gather conv patches (blocks [0,4096)) + x1 split
// (blocks [4096,6144)). Grid 6144 x 256.
// ---------------------------------------------------------------------------
__global__ void prep_inputs_kernel(const float* __restrict__ x1,
                                   const float* __restrict__ x2) {
    int bx = blockIdx.x, t = threadIdx.x;
    if (bx < 4096) {
        unsigned idx = bx * 256 + t;       // float4 index, 2^20 total
        int k4  = idx & 255;
        int m   = (idx >> 8) & 1023;
        int b   = (idx >> 18) & 1;
        int src = (idx >> 19) & 1;
        int seg = k4 >> 6;
        int ci4 = k4 & 63;
        int i = m >> 5, j = m & 31;
        int kh = seg >> 1, kw = seg & 1;
        int n = (2 * i + kh) * 64 + 2 * j + kw;
        const float* sp = src ? x2 : x1;
        float4 v = *(const float4*)(sp + ((long)b * Nn + n) * Cc + ci4 * 4);
        ((uint32_t*)g_gah)[idx * 2]     = pack_split_hi(v.x, v.y);
        ((uint32_t*)g_gah)[idx * 2 + 1] = pack_split_hi(v.z, v.w);
        ((uint32_t*)g_gal)[idx * 2]     = pack_split_lo(v.x, v.y);
        ((uint32_t*)g_gal)[idx * 2 + 1] = pack_split_lo(v.z, v.w);
    } else {
        split4_at(x1, g_x1h, g_x1l, (bx - 4096) * 256 + t);
    }
}

// ---------------------------------------------------------------------------
// mma.sync GEMM, bf16x2 split emulation of fp32.  (validated R3/R7)
// gridDim.z batching: pointers advance by sA/sW/sC per z slice.
// ---------------------------------------------------------------------------
constexpr int AST = 40;   // smem stride in halves (80B rows)

template <bool SPLIT>
__global__ __launch_bounds__(256) void gemm_mma_kernel(
    const __nv_bfloat16* __restrict__ Ah, const __nv_bfloat16* __restrict__ Al,
    const __nv_bfloat16* __restrict__ Wh, const __nv_bfloat16* __restrict__ Wl,
    const float* __restrict__ bias, float* __restrict__ Cout,
    __nv_bfloat16* __restrict__ Ch, __nv_bfloat16* __restrict__ Cl,
    int Ndim, int K, long sA, long sW, long sC)
{
    __shared__ __nv_bfloat16 sAh[128 * AST], sAl[128 * AST];
    __shared__ __nv_bfloat16 sWh[64 * AST],  sWl[64 * AST];
    __shared__ float sbias[64];

    long zo = (long)blockIdx.z;
    Ah += zo * sA; Al += zo * sA;
    Wh += zo * sW; Wl += zo * sW;
    if (SPLIT) { Ch += zo * sC; Cl += zo * sC; }
    else if (Cout) Cout += zo * sC;

    int tid = threadIdx.x, lane = tid & 31, wid = tid >> 5;
    int wm = wid >> 1, wn = wid & 1;
    int m0 = blockIdx.x * 128, n0 = blockIdx.y * 64;

    if (tid < 64) sbias[tid] = bias ? bias[n0 + tid] : 0.f;

    float acc[2][4][4];
#pragma unroll
    for (int mt = 0; mt < 2; mt++)
#pragma unroll
        for (int nt = 0; nt < 4; nt++)
#pragma unroll
            for (int e = 0; e < 4; e++) acc[mt][nt][e] = 0.f;

    int a_row  = wm * 32 + (lane & 15);
    int a_colb = (lane >> 4) << 3;
    int b_row  = wn * 32 + ((lane >> 4) << 3) + (lane & 7);
    int b_colb = ((lane >> 3) & 1) << 3;

    uint32_t sa_h = smem_u32(sAh), sa_l = smem_u32(sAl);
    uint32_t sb_h = smem_u32(sWh), sb_l = smem_u32(sWl);

    int ar = tid >> 1, ahalf = tid & 1;
    int brr = tid >> 2, bq = tid & 3;

    for (int k0 = 0; k0 < K; k0 += 32) {
        {
            size_t ga = (size_t)(m0 + ar) * K + k0 + ahalf * 16;
            const uint4* pAh = (const uint4*)(Ah + ga);
            const uint4* pAl = (const uint4*)(Al + ga);
            *(uint4*)&sAh[ar * AST + ahalf * 16]     = pAh[0];
            *(uint4*)&sAh[ar * AST + ahalf * 16 + 8] = pAh[1];
            *(uint4*)&sAl[ar * AST + ahalf * 16]     = pAl[0];
            *(uint4*)&sAl[ar * AST + ahalf * 16 + 8] = pAl[1];
            size_t gb = (size_t)(n0 + brr) * K + k0 + bq * 8;
            *(uint4*)&sWh[brr * AST + bq * 8] = *(const uint4*)(Wh + gb);
            *(uint4*)&sWl[brr * AST + bq * 8] = *(const uint4*)(Wl + gb);
        }
        __syncthreads();

#pragma unroll
        for (int ks = 0; ks < 32; ks += 16) {
            uint32_t aH[2][4], aL[2][4], bH[4][2], bL[4][2];
#pragma unroll
            for (int mt = 0; mt < 2; mt++) {
                uint32_t off = (uint32_t)(((a_row + mt * 16) * AST + ks + a_colb) * 2);
                LDSM_X4(aH[mt][0], aH[mt][1], aH[mt][2], aH[mt][3], sa_h + off);
                LDSM_X4(aL[mt][0], aL[mt][1], aL[mt][2], aL[mt][3], sa_l + off);
            }
#pragma unroll
            for (int p = 0; p < 2; p++) {
                uint32_t off = (uint32_t)(((b_row + p * 16) * AST + ks + b_colb) * 2);
                uint32_t r0, r1, r2, r3;
                LDSM_X4(r0, r1, r2, r3, sb_h + off);
                bH[p * 2][0] = r0; bH[p * 2][1] = r1;
                bH[p * 2 + 1][0] = r2; bH[p * 2 + 1][1] = r3;
                LDSM_X4(r0, r1, r2, r3, sb_l + off);
                bL[p * 2][0] = r0; bL[p * 2][1] = r1;
                bL[p * 2 + 1][0] = r2; bL[p * 2 + 1][1] = r3;
            }
#pragma unroll
            for (int mt = 0; mt < 2; mt++)
#pragma unroll
                for (int nt = 0; nt < 4; nt++) {
                    MMA_BF16(acc[mt][nt], aH[mt], bH[nt]);
                    MMA_BF16(acc[mt][nt], aH[mt], bL[nt]);
                    MMA_BF16(acc[mt][nt], aL[mt], bH[nt]);
                }
        }
        __syncthreads();
    }

    int g = lane >> 2, tig = lane & 3;
#pragma unroll
    for (int mt = 0; mt < 2; mt++)
#pragma unroll
        for (int hf = 0; hf < 2; hf++) {
            int row = m0 + wm * 32 + mt * 16 + g + hf * 8;
#pragma unroll
            for (int nt = 0; nt < 4; nt++) {
                int cb = wn * 32 + nt * 8 + tig * 2;
                float ox = acc[mt][nt][hf * 2 + 0] + sbias[cb];
                float oy = acc[mt][nt][hf * 2 + 1] + sbias[cb + 1];
                size_t e = (size_t)row * Ndim + n0 + cb;
                if (SPLIT) {
                    *(uint32_t*)(Ch + e) = pack_split_hi(ox, oy);
                    *(uint32_t*)(Cl + e) = pack_split_lo(ox, oy);
                } else {
                    float2 o; o.x = ox; o.y = oy;
                    *(float2*)(Cout + e) = o;
                }
            }
        }
}

// ---------------------------------------------------------------------------
// LayerNorm over rows of g_xr (4096 x 256); writes bf16 hi/lo splits.
// ---------------------------------------------------------------------------
__global__ __launch_bounds__(256) void layernorm_kernel(
    const float* __restrict__ g, const float* __restrict__ b)
{
    int warp = threadIdx.x >> 5, lane = threadIdx.x & 31;
    long row = (long)blockIdx.x * 8 + warp;
    const float* p = g_xr + row * 256;

    float4 v0 = ((const float4*)p)[lane];
    float4 v1 = ((const float4*)p)[lane + 32];
    float s  = v0.x + v0.y + v0.z + v0.w + v1.x + v1.y + v1.z + v1.w;
    float sq = v0.x * v0.x + v0.y * v0.y + v0.z * v0.z + v0.w * v0.w +
               v1.x * v1.x + v1.y * v1.y + v1.z * v1.z + v1.w * v1.w;
#pragma unroll
    for (int off = 16; off; off >>= 1) {
        s  += __shfl_xor_sync(0xffffffffu, s, off);
        sq += __shfl_xor_sync(0xffffffffu, sq, off);
    }
    float mu = s * (1.f / 256.f);
    float var = sq * (1.f / 256.f) - mu * mu;
    float rs = rsqrtf(var + 1e-5f);

    float4 g0 = ((const float4*)g)[lane];
    float4 b0 = ((const float4*)b)[lane];
    float4 g1 = ((const float4*)g)[lane + 32];
    float4 b1 = ((const float4*)b)[lane + 32];
    float o[8];
    o[0] = (v0.x - mu) * rs * g0.x + b0.x;
    o[1] = (v0.y - mu) * rs * g0.y + b0.y;
    o[2] = (v0.z - mu) * rs * g0.z + b0.z;
    o[3] = (v0.w - mu) * rs * g0.w + b0.w;
    o[4] = (v1.x - mu) * rs * g1.x + b1.x;
    o[5] = (v1.y - mu) * rs * g1.y + b1.y;
    o[6] = (v1.z - mu) * rs * g1.z + b1.z;
    o[7] = (v1.w - mu) * rs * g1.w + b1.w;

    long e0 = row * 256 + lane * 4;
    long e1 = row * 256 + (lane + 32) * 4;
#pragma unroll
    for (int half = 0; half < 2; half++) {
        long e = half ? e1 : e0;
        const float* ov = o + half * 4;
        *(uint32_t*)(g_xrh + e)     = pack_split_hi(ov[0], ov[1]);
        *(uint32_t*)(g_xrh + e + 2) = pack_split_hi(ov[2], ov[3]);
        *(uint32_t*)(g_xrl + e)     = pack_split_lo(ov[0], ov[1]);
        *(uint32_t*)(g_xrl + e + 2) = pack_split_lo(ov[2], ov[3]);
    }
}

// ---------------------------------------------------------------------------
// Flash attention v3: MMA QK^T and P.V (R7-validated ldmatrix patterns),
// softmax fully in registers (quad shfl over tig), P repacked c-frag->a-frag
// in registers. No S/P smem round trip; 2 barriers per chunk (was 4).
// CTA = 128 q-rows x one (b,h); 8 warps; 32 key-chunks of 32.
// ---------------------------------------------------------------------------
__global__ __launch_bounds__(256) void attention_mma3_kernel() {
    __shared__ __nv_bfloat16 sQh[128 * AST], sQl[128 * AST];
    __shared__ __nv_bfloat16 sKh[32 * AST],  sKl[32 * AST];
    __shared__ __nv_bfloat16 sVth[32 * AST], sVtl[32 * AST];

    int tid = threadIdx.x, lane = tid & 31, wid = tid >> 5;
    int n0 = blockIdx.x * 128, h = blockIdx.y, b = blockIdx.z;
    int g = lane >> 2, tig = lane & 3;
    const float scale = 0.17677669529663689f;   // 1/sqrt(32)

    const __nv_bfloat16* QhG = g_qh  + ((long)b * Nn + n0) * Cc + h * 32;
    const __nv_bfloat16* QlG = g_ql  + ((long)b * Nn + n0) * Cc + h * 32;
    const __nv_bfloat16* KhG = g_kvh + (long)b * Mm * Cc + h * 32;          // k2
    const __nv_bfloat16* KlG = g_kvl + (long)b * Mm * Cc + h * 32;
    const __nv_bfloat16* VhG = g_kvh + BMC + (long)b * Mm * Cc + h * 32;    // v1
    const __nv_bfloat16* VlG = g_kvl + BMC + (long)b * Mm * Cc + h * 32;

    // Load Q tile (128 x 32) hi/lo into smem — full 32 cols per row
    {
        int r = tid >> 1, hf = tid & 1;
        const __nv_bfloat16* qs = QhG + (long)r * Cc + hf * 16;
        *(uint4*)&sQh[r * AST + hf * 16]     = *(const uint4*)(qs);
        *(uint4*)&sQh[r * AST + hf * 16 + 8] = *(const uint4*)(qs + 8);
        const __nv_bfloat16* qsl = QlG + (long)r * Cc + hf * 16;
        *(uint4*)&sQl[r * AST + hf * 16]     = *(const uint4*)(qsl);
        *(uint4*)&sQl[r * AST + hf * 16 + 8] = *(const uint4*)(qsl + 8);
    }
    __syncthreads();

    // Persistent Q a-frags
    uint32_t qh[2][4], ql[2][4];
    {
        int a_row = wid * 16 + (lane & 15);
        int a_colb = (lane >> 4) << 3;
        uint32_t sq_h = smem_u32(sQh), sq_l = smem_u32(sQl);
#pragma unroll
        for (int ks = 0; ks < 2; ks++) {
            uint32_t off = (uint32_t)((a_row * AST + ks * 16 + a_colb) * 2);
            LDSM_X4(qh[ks][0], qh[ks][1], qh[ks][2], qh[ks][3], sq_h + off);
            LDSM_X4(ql[ks][0], ql[ks][1], ql[ks][2], ql[ks][3], sq_l + off);
        }
    }

    float mrun[2] = {-1e30f, -1e30f}, lrun[2] = {0.f, 0.f};
    float O[4][4];
#pragma unroll
    for (int dt = 0; dt < 4; dt++)
#pragma unroll
        for (int e = 0; e < 4; e++) O[dt][e] = 0.f;

    uint32_t sk_h = smem_u32(sKh), sk_l = smem_u32(sKl);
    uint32_t sv_h = smem_u32(sVth), sv_l = smem_u32(sVtl);

    // validated B-pattern addressing (same formula as GEMM W path)
    int b_row  = ((lane >> 4) << 3) + (lane & 7);
    int b_colb = ((lane >> 3) & 1) << 3;

    for (int mc = 0; mc < Mm / 32; mc++) {
        __syncthreads();   // prior chunk's smem reads complete

        // ---- load K (full 32 cols per row) ----
        if (tid < 128) {
            int buf = tid >> 6;            // 0: hi, 1: lo
            int i = tid & 63, r = i >> 1, hf = i & 1;
            const __nv_bfloat16* src = (buf ? KlG : KhG)
                + (long)(mc * 32 + r) * Cc + hf * 16;
            __nv_bfloat16* dst = buf ? sKl : sKh;
            *(uint4*)&dst[r * AST + hf * 16]     = *(const uint4*)(src);
            *(uint4*)&dst[r * AST + hf * 16 + 8] = *(const uint4*)(src + 8);
        }
        // ---- load V transposed to [d][key] ----
        {
            int buf = tid >> 7;            // 0: hi, 1: lo
            int i = tid & 127, k = i & 31, dg = i >> 5;   // dg: d block of 8
            const __nv_bfloat16* src = buf ? VlG : VhG;
            __nv_bfloat16* dst = buf ? sVtl : sVth;
            uint4 v = *(const uint4*)(src + (long)(mc * 32 + k) * Cc + dg * 8);
            const __nv_bfloat16* hv = (const __nv_bfloat16*)&v;
#pragma unroll
            for (int j = 0; j < 8; j++)
                dst[(dg * 8 + j) * AST + k] = hv[j];
        }
        __syncthreads();

        // ---- S = Q @ K^T (3-pass split) ----
        float s[4][4];
#pragma unroll
        for (int nt = 0; nt < 4; nt++)
#pragma unroll
            for (int e = 0; e < 4; e++) s[nt][e] = 0.f;

#pragma unroll
        for (int ks = 0; ks < 2; ks++) {
            uint32_t kh[4][2], kl[4][2];
#pragma unroll
            for (int grp = 0; grp < 2; grp++) {
                uint32_t off = (uint32_t)(((grp * 16 + b_row) * AST + ks * 16 + b_colb) * 2);
                uint32_t r0, r1, r2, r3;
                LDSM_X4(r0, r1, r2, r3, sk_h + off);
                kh[grp * 2][0] = r0; kh[grp * 2][1] = r1;
                kh[grp * 2 + 1][0] = r2; kh[grp * 2 + 1][1] = r3;
                LDSM_X4(r0, r1, r2, r3, sk_l + off);
                kl[grp * 2][0] = r0; kl[grp * 2][1] = r1;
                kl[grp * 2 + 1][0] = r2; kl[grp * 2 + 1][1] = r3;
            }
#pragma unroll
            for (int nt = 0; nt < 4; nt++) {
                MMA_BF16(s[nt], qh[ks], kh[nt]);
                MMA_BF16(s[nt], qh[ks], kl[nt]);
                MMA_BF16(s[nt], ql[ks], kh[nt]);
            }
        }

        // ---- in-register online softmax (rows g, g+8; quad reduce) ----
        float p[4][4];
#pragma unroll
        for (int rh = 0; rh < 2; rh++) {
            float mx = -1e30f;
#pragma unroll
            for (int nt = 0; nt < 4; nt++)
                mx = fmaxf(mx, fmaxf(s[nt][rh * 2] * scale,
                                     s[nt][rh * 2 + 1] * scale));
            mx = fmaxf(mx, __shfl_xor_sync(0xffffffffu, mx, 1));
            mx = fmaxf(mx, __shfl_xor_sync(0xffffffffu, mx, 2));
            float mnew = fmaxf(mrun[rh], mx);
            float alpha = __expf(mrun[rh] - mnew);
            mrun[rh] = mnew;
            float sum = 0.f;
#pragma unroll
            for (int nt = 0; nt < 4; nt++) {
                float p0 = __expf(s[nt][rh * 2] * scale - mnew);
                float p1 = __expf(s[nt][rh * 2 + 1] * scale - mnew);
                p[nt][rh * 2] = p0;
                p[nt][rh * 2 + 1] = p1;
                sum += p0 + p1;
            }
            sum += __shfl_xor_sync(0xffffffffu, sum, 1);
            sum += __shfl_xor_sync(0xffffffffu, sum, 2);
            lrun[rh] = lrun[rh] * alpha + sum;
#pragma unroll
            for (int dt = 0; dt < 4; dt++) {
                O[dt][rh * 2]     *= alpha;
                O[dt][rh * 2 + 1] *= alpha;
            }
        }

        // ---- O += P @ Vt (P repacked c-frag -> a-frag in registers) ----
#pragma unroll
        for (int ks = 0; ks < 2; ks++) {
            uint32_t pah[4], pal[4];
            pah[0] = pack_split_hi(p[2 * ks][0], p[2 * ks][1]);
            pah[1] = pack_split_hi(p[2 * ks][2], p[2 * ks][3]);
            pah[2] = pack_split_hi(p[2 * ks + 1][0], p[2 * ks + 1][1]);
            pah[3] = pack_split_hi(p[2 * ks + 1][2], p[2 * ks + 1][3]);
            pal[0] = pack_split_lo(p[2 * ks][0], p[2 * ks][1]);
            pal[1] = pack_split_lo(p[2 * ks][2], p[2 * ks][3]);
            pal[2] = pack_split_lo(p[2 * ks + 1][0], p[2 * ks + 1][1]);
            pal[3] = pack_split_lo(p[2 * ks + 1][2], p[2 * ks + 1][3]);

            uint32_t vh[4][2], vl[4][2];
#pragma unroll
            for (int dblk = 0; dblk < 2; dblk++) {
                uint32_t off = (uint32_t)(((dblk * 16 + b_row) * AST + ks * 16 + b_colb) * 2);
                uint32_t r0, r1, r2, r3;
                LDSM_X4(r0, r1, r2, r3, sv_h + off);
                vh[dblk * 2][0] = r0; vh[dblk * 2][1] = r1;
                vh[dblk * 2 + 1][0] = r2; vh[dblk * 2 + 1][1] = r3;
                LDSM_X4(r0, r1, r2, r3, sv_l + off);
                vl[dblk * 2][0] = r0; vl[dblk * 2][1] = r1;
                vl[dblk * 2 + 1][0] = r2; vl[dblk * 2 + 1][1] = r3;
            }
#pragma unroll
            for (int dt = 0; dt < 4; dt++) {
                MMA_BF16(O[dt], pah, vh[dt]);
                MMA_BF16(O[dt], pah, vl[dt]);
                MMA_BF16(O[dt], pal, vh[dt]);
            }
        }
    }

    // ---- epilogue: normalize + split to bf16 hi/lo ----
    long base = ((long)b * Nn + n0) * Cc + h * 32;
#pragma unroll
    for (int rh = 0; rh < 2; rh++) {
        float inv = 1.f / lrun[rh];
        int row = wid * 16 + g + rh * 8;
#pragma unroll
        for (int dt = 0; dt < 4; dt++) {
            float ox = O[dt][rh * 2] * inv;
            float oy = O[dt][rh * 2 + 1] * inv;
            long e = base + (long)row * Cc + dt * 8 + tig * 2;
            *(uint32_t*)(g_ath + e) = pack_split_hi(ox, oy);
            *(uint32_t*)(g_atl + e) = pack_split_lo(ox, oy);
        }
    }
}

// ---------------------------------------------------------------------------
extern "C" void kernel_launch(void* const* d_in, const int* in_sizes, int n_in,
                              void* d_out, int out_size) {
    const float* x1     = (const float*)d_in[0];
    const float* x2     = (const float*)d_in[1];
    const float* q_w    = (const float*)d_in[2];
    const float* kv_w   = (const float*)d_in[3];
    const float* sr_w   = (const float*)d_in[4];
    const float* sr_b   = (const float*)d_in[5];
    const float* ln_g   = (const float*)d_in[6];
    const float* ln_b   = (const float*)d_in[7];
    const float* proj_w = (const float*)d_in[8];
    const float* proj_b = (const float*)d_in[9];
    float* out = (float*)d_out;

    float* p_xr;
    cudaGetSymbolAddress((void**)&p_xr, g_xr);
    __nv_bfloat16 *p_x1h, *p_x1l, *p_gah, *p_gal, *p_srh, *p_srl;
    __nv_bfloat16 *p_xrh, *p_xrl, *p_ath, *p_atl;
    __nv_bfloat16 *p_qh, *p_ql, *p_kvh, *p_kvl;
    __nv_bfloat16 *p_qwh, *p_qwl, *p_kwh, *p_kwl, *p_pwh, *p_pwl;
    cudaGetSymbolAddress((void**)&p_x1h, g_x1h);
    cudaGetSymbolAddress((void**)&p_x1l, g_x1l);
    cudaGetSymbolAddress((void**)&p_gah, g_gah);
    cudaGetSymbolAddress((void**)&p_gal, g_gal);
    cudaGetSymbolAddress((void**)&p_srh, g_srh);
    cudaGetSymbolAddress((void**)&p_srl, g_srl);
    cudaGetSymbolAddress((void**)&p_xrh, g_xrh);
    cudaGetSymbolAddress((void**)&p_xrl, g_xrl);
    cudaGetSymbolAddress((void**)&p_ath, g_ath);
    cudaGetSymbolAddress((void**)&p_atl, g_atl);
    cudaGetSymbolAddress((void**)&p_qh, g_qh);
    cudaGetSymbolAddress((void**)&p_ql, g_ql);
    cudaGetSymbolAddress((void**)&p_kvh, g_kvh);
    cudaGetSymbolAddress((void**)&p_kvl, g_kvl);
    cudaGetSymbolAddress((void**)&p_qwh, g_qwh);
    cudaGetSymbolAddress((void**)&p_qwl, g_qwl);
    cudaGetSymbolAddress((void**)&p_kwh, g_kwh);
    cudaGetSymbolAddress((void**)&p_kwl, g_kwl);
    cudaGetSymbolAddress((void**)&p_pwh, g_pwh);
    cudaGetSymbolAddress((void**)&p_pwl, g_pwl);

    // 1) fused prep (weights + inputs)
    prep_weights_kernel<<<1280, 256>>>(sr_w, q_w, kv_w, proj_w);
    prep_inputs_kernel<<<6144, 256>>>(x1, x2);

    // 2) q = x1 @ q_w^T  -> bf16 hi/lo
    gemm_mma_kernel<true><<<dim3(64, 4), 256>>>(
        p_x1h, p_x1l, p_qwh, p_qwl, nullptr, nullptr, p_qh, p_ql,
        Cc, Cc, 0, 0, 0);
    // 3) conv-as-GEMM + bias -> fp32 (pre-LN)
    gemm_mma_kernel<false><<<dim3(32, 4), 256>>>(
        p_gah, p_gal, p_srh, p_srl, sr_b, p_xr, nullptr, nullptr,
        Cc, Kc, 0, 0, 0);
    // 4) layernorm -> bf16 splits
    layernorm_kernel<<<512, 256>>>(ln_g, ln_b);
    // 5) batched: z=0: k2 = x2r @ kv_w[0:256]^T ; z=1: v1 = x1r @ kv_w[256:]^T
    gemm_mma_kernel<true><<<dim3(16, 4, 2), 256>>>(
        p_xrh + BMC, p_xrl + BMC, p_kwh, p_kwl,
        nullptr, nullptr, p_kvh, p_kvl,
        Cc, Cc, -BMC, (long)Cc * Cc, BMC);
    // 6) flash attention v3 (MMA + in-register softmax) -> bf16 splits
    attention_mma3_kernel<<<dim3(Nn / 128, Hh, Bb), 256>>>();
    // 7) out = attn @ proj_w^T + proj_b
    gemm_mma_kernel<false><<<dim3(64, 4), 256>>>(
        p_ath, p_atl, p_pwh, p_pwl, proj_b, out, nullptr, nullptr,
        Cc, Cc, 0, 0, 0);
}

// round 9
// speedup vs baseline: 2.5426x; 1.1215x over previous
#include <cuda_runtime.h>
#include <cuda_bf16.h>
#include <cstdint>
#include <math.h>

// Problem constants
constexpr int Bb = 2;
constexpr int Nn = 4096;
constexpr int Cc = 256;
constexpr int Hh = 8;
constexpr int Mm = 1024;      // reduced tokens (32x32)
constexpr int Kc = 1024;      // conv-as-GEMM K (4 * 256)
constexpr long BMC = (long)Bb * Mm * Cc;

// -------- scratch (static device allocations; no cudaMalloc allowed) --------
__device__ float g_xr  [2 * Bb * Mm * Cc];      // fp32 conv output (pre-LN)

__device__ __nv_bfloat16 g_x1h [Bb * Nn * Cc];      // x1 split
__device__ __nv_bfloat16 g_x1l [Bb * Nn * Cc];
__device__ __nv_bfloat16 g_gah [2 * Bb * Mm * Kc];  // gathered patches split
__device__ __nv_bfloat16 g_gal [2 * Bb * Mm * Kc];
__device__ __nv_bfloat16 g_srh [Cc * Kc];           // packed sr_w split
__device__ __nv_bfloat16 g_srl [Cc * Kc];
__device__ __nv_bfloat16 g_xrh [2 * Bb * Mm * Cc];  // post-LN split
__device__ __nv_bfloat16 g_xrl [2 * Bb * Mm * Cc];
__device__ __nv_bfloat16 g_qh  [Bb * Nn * Cc];      // q split (from q GEMM)
__device__ __nv_bfloat16 g_ql  [Bb * Nn * Cc];
__device__ __nv_bfloat16 g_kvh [2 * Bb * Mm * Cc];  // [0]: k2, [1]: v1  (hi)
__device__ __nv_bfloat16 g_kvl [2 * Bb * Mm * Cc];  // (lo)
__device__ __nv_bfloat16 g_ath [Bb * Nn * Cc];      // attention out split
__device__ __nv_bfloat16 g_atl [Bb * Nn * Cc];
__device__ __nv_bfloat16 g_qwh [Cc * Cc];
__device__ __nv_bfloat16 g_qwl [Cc * Cc];
__device__ __nv_bfloat16 g_kwh [2 * Cc * Cc];
__device__ __nv_bfloat16 g_kwl [2 * Cc * Cc];
__device__ __nv_bfloat16 g_pwh [Cc * Cc];
__device__ __nv_bfloat16 g_pwl [Cc * Cc];

// ---------------------------------------------------------------------------
__device__ __forceinline__ uint32_t smem_u32(const void* p) {
    uint32_t a;
    asm("{ .reg .u64 t; cvta.to.shared.u64 t, %1; cvt.u32.u64 %0, t; }"
        : "=r"(a) : "l"(p));
    return a;
}
__device__ __forceinline__ void split2(float v, __nv_bfloat16& h, __nv_bfloat16& l) {
    h = __float2bfloat16(v);
    l = __float2bfloat16(v - __bfloat162float(h));
}
__device__ __forceinline__ uint32_t pack_split_hi(float a, float b) {
    __nv_bfloat162 p;
    p.x = __float2bfloat16(a);
    p.y = __float2bfloat16(b);
    return *(uint32_t*)&p;
}
__device__ __forceinline__ uint32_t pack_split_lo(float a, float b) {
    __nv_bfloat162 p;
    p.x = __float2bfloat16(a - __bfloat162float(__float2bfloat16(a)));
    p.y = __float2bfloat16(b - __bfloat162float(__float2bfloat16(b)));
    return *(uint32_t*)&p;
}
__device__ __forceinline__ void split4_at(const float* __restrict__ in,
                                          __nv_bfloat16* __restrict__ oh,
                                          __nv_bfloat16* __restrict__ ol, int idx) {
    float4 v = ((const float4*)in)[idx];
    ((uint32_t*)oh)[idx * 2]     = pack_split_hi(v.x, v.y);
    ((uint32_t*)oh)[idx * 2 + 1] = pack_split_hi(v.z, v.w);
    ((uint32_t*)ol)[idx * 2]     = pack_split_lo(v.x, v.y);
    ((uint32_t*)ol)[idx * 2 + 1] = pack_split_lo(v.z, v.w);
}

#define LDSM_X4(r0, r1, r2, r3, addr) \
    asm volatile("ldmatrix.sync.aligned.m8n8.x4.shared.b16 {%0,%1,%2,%3}, [%4];" \
                 : "=r"(r0), "=r"(r1), "=r"(r2), "=r"(r3) : "r"(addr))

#define MMA_BF16(c, a, b) \
    asm volatile("mma.sync.aligned.m16n8k16.row.col.f32.bf16.bf16.f32 " \
                 "{%0,%1,%2,%3}, {%4,%5,%6,%7}, {%8,%9}, {%0,%1,%2,%3};" \
                 : "+f"((c)[0]), "+f"((c)[1]), "+f"((c)[2]), "+f"((c)[3]) \
                 : "r"((a)[0]), "r"((a)[1]), "r"((a)[2]), "r"((a)[3]), \
                   "r"((b)[0]), "r"((b)[1]))

// ---------------------------------------------------------------------------
// Fused weight prep: pack+split sr_w, split q_w / kv_w / proj_w.
// ---------------------------------------------------------------------------
__global__ void prep_weights_kernel(const float* __restrict__ srw,
                                    const float* __restrict__ qw,
                                    const float* __restrict__ kvw,
                                    const float* __restrict__ pw) {
    int bx = blockIdx.x, t = threadIdx.x;
    if (bx < 1024) {                       // pack sr_w
        int idx = bx * 256 + t;
        int co = idx >> 10;
        int k  = idx & 1023;
        int seg = k >> 8;
        int ci  = k & 255;
        float v = srw[((co << 8) + ci) * 4 + seg];
        __nv_bfloat16 h, l;
        split2(v, h, l);
        g_srh[idx] = h;
        g_srl[idx] = l;
    } else if (bx < 1088) {
        split4_at(qw, g_qwh, g_qwl, (bx - 1024) * 256 + t);
    } else if (bx < 1216) {
        split4_at(kvw, g_kwh, g_kwl, (bx - 1088) * 256 + t);
    } else {
        split4_at(pw, g_pwh, g_pwl, (bx - 1216) * 256 + t);
    }
}

// ---------------------------------------------------------------------------
// Fused input prep: gather conv patches + x1 split.
// ---------------------------------------------------------------------------
__global__ void prep_inputs_kernel(const float* __restrict__ x1,
                                   const float* __restrict__ x2) {
    int bx = blockIdx.x, t = threadIdx.x;
    if (bx < 4096) {
        unsigned idx = bx * 256 + t;
        int k4  = idx & 255;
        int m   = (idx >> 8) & 1023;
        int b   = (idx >> 18) & 1;
        int src = (idx >> 19) & 1;
        int seg = k4 >> 6;
        int ci4 = k4 & 63;
        int i = m >> 5, j = m & 31;
        int kh = seg >> 1, kw = seg & 1;
        int n = (2 * i + kh) * 64 + 2 * j + kw;
        const float* sp = src ? x2 : x1;
        float4 v = *(const float4*)(sp + ((long)b * Nn + n) * Cc + ci4 * 4);
        ((uint32_t*)g_gah)[idx * 2]     = pack_split_hi(v.x, v.y);
        ((uint32_t*)g_gah)[idx * 2 + 1] = pack_split_hi(v.z, v.w);
        ((uint32_t*)g_gal)[idx * 2]     = pack_split_lo(v.x, v.y);
        ((uint32_t*)g_gal)[idx * 2 + 1] = pack_split_lo(v.z, v.w);
    } else {
        split4_at(x1, g_x1h, g_x1l, (bx - 4096) * 256 + t);
    }
}

// ---------------------------------------------------------------------------
// mma.sync GEMM with register-prefetch double buffering.
// Load chunk ch+1 into regs BEFORE computing chunk ch; commit regs->smem
// after compute. Global-load latency hides under the MMA phase.
// ---------------------------------------------------------------------------
constexpr int AST = 40;   // smem stride in halves (80B rows)

template <bool SPLIT>
__global__ __launch_bounds__(256) void gemm_mma_kernel(
    const __nv_bfloat16* __restrict__ Ah, const __nv_bfloat16* __restrict__ Al,
    const __nv_bfloat16* __restrict__ Wh, const __nv_bfloat16* __restrict__ Wl,
    const float* __restrict__ bias, float* __restrict__ Cout,
    __nv_bfloat16* __restrict__ Ch, __nv_bfloat16* __restrict__ Cl,
    int Ndim, int K, long sA, long sW, long sC)
{
    __shared__ __nv_bfloat16 sAh[128 * AST], sAl[128 * AST];
    __shared__ __nv_bfloat16 sWh[64 * AST],  sWl[64 * AST];
    __shared__ float sbias[64];

    long zo = (long)blockIdx.z;
    Ah += zo * sA; Al += zo * sA;
    Wh += zo * sW; Wl += zo * sW;
    if (SPLIT) { Ch += zo * sC; Cl += zo * sC; }
    else if (Cout) Cout += zo * sC;

    int tid = threadIdx.x, lane = tid & 31, wid = tid >> 5;
    int wm = wid >> 1, wn = wid & 1;
    int m0 = blockIdx.x * 128, n0 = blockIdx.y * 64;

    if (tid < 64) sbias[tid] = bias ? bias[n0 + tid] : 0.f;

    float acc[2][4][4];
#pragma unroll
    for (int mt = 0; mt < 2; mt++)
#pragma unroll
        for (int nt = 0; nt < 4; nt++)
#pragma unroll
            for (int e = 0; e < 4; e++) acc[mt][nt][e] = 0.f;

    int a_row  = wm * 32 + (lane & 15);
    int a_colb = (lane >> 4) << 3;
    int b_row  = wn * 32 + ((lane >> 4) << 3) + (lane & 7);
    int b_colb = ((lane >> 3) & 1) << 3;

    uint32_t sa_h = smem_u32(sAh), sa_l = smem_u32(sAl);
    uint32_t sb_h = smem_u32(sWh), sb_l = smem_u32(sWl);

    int ar = tid >> 1, ahalf = tid & 1;
    int brr = tid >> 2, bq = tid & 3;

    const __nv_bfloat16* pAhB = Ah + (size_t)(m0 + ar) * K + ahalf * 16;
    const __nv_bfloat16* pAlB = Al + (size_t)(m0 + ar) * K + ahalf * 16;
    const __nv_bfloat16* pWhB = Wh + (size_t)(n0 + brr) * K + bq * 8;
    const __nv_bfloat16* pWlB = Wl + (size_t)(n0 + brr) * K + bq * 8;

    uint4 rA0h, rA1h, rA0l, rA1l, rW0h, rW0l;
    // prologue: prefetch chunk 0
    rA0h = *(const uint4*)(pAhB);     rA1h = *(const uint4*)(pAhB + 8);
    rA0l = *(const uint4*)(pAlB);     rA1l = *(const uint4*)(pAlB + 8);
    rW0h = *(const uint4*)(pWhB);     rW0l = *(const uint4*)(pWlB);

    for (int k0 = 0; k0 < K; k0 += 32) {
        // commit prefetched chunk to smem
        *(uint4*)&sAh[ar * AST + ahalf * 16]     = rA0h;
        *(uint4*)&sAh[ar * AST + ahalf * 16 + 8] = rA1h;
        *(uint4*)&sAl[ar * AST + ahalf * 16]     = rA0l;
        *(uint4*)&sAl[ar * AST + ahalf * 16 + 8] = rA1l;
        *(uint4*)&sWh[brr * AST + bq * 8] = rW0h;
        *(uint4*)&sWl[brr * AST + bq * 8] = rW0l;
        __syncthreads();

        // prefetch next chunk (latency hidden under compute below)
        if (k0 + 32 < K) {
            rA0h = *(const uint4*)(pAhB + k0 + 32);
            rA1h = *(const uint4*)(pAhB + k0 + 32 + 8);
            rA0l = *(const uint4*)(pAlB + k0 + 32);
            rA1l = *(const uint4*)(pAlB + k0 + 32 + 8);
            rW0h = *(const uint4*)(pWhB + k0 + 32);
            rW0l = *(const uint4*)(pWlB + k0 + 32);
        }

#pragma unroll
        for (int ks = 0; ks < 32; ks += 16) {
            uint32_t aH[2][4], aL[2][4], bH[4][2], bL[4][2];
#pragma unroll
            for (int mt = 0; mt < 2; mt++) {
                uint32_t off = (uint32_t)(((a_row + mt * 16) * AST + ks + a_colb) * 2);
                LDSM_X4(aH[mt][0], aH[mt][1], aH[mt][2], aH[mt][3], sa_h + off);
                LDSM_X4(aL[mt][0], aL[mt][1], aL[mt][2], aL[mt][3], sa_l + off);
            }
#pragma unroll
            for (int p = 0; p < 2; p++) {
                uint32_t off = (uint32_t)(((b_row + p * 16) * AST + ks + b_colb) * 2);
                uint32_t r0, r1, r2, r3;
                LDSM_X4(r0, r1, r2, r3, sb_h + off);
                bH[p * 2][0] = r0; bH[p * 2][1] = r1;
                bH[p * 2 + 1][0] = r2; bH[p * 2 + 1][1] = r3;
                LDSM_X4(r0, r1, r2, r3, sb_l + off);
                bL[p * 2][0] = r0; bL[p * 2][1] = r1;
                bL[p * 2 + 1][0] = r2; bL[p * 2 + 1][1] = r3;
            }
#pragma unroll
            for (int mt = 0; mt < 2; mt++)
#pragma unroll
                for (int nt = 0; nt < 4; nt++) {
                    MMA_BF16(acc[mt][nt], aH[mt], bH[nt]);
                    MMA_BF16(acc[mt][nt], aH[mt], bL[nt]);
                    MMA_BF16(acc[mt][nt], aL[mt], bH[nt]);
                }
        }
        __syncthreads();
    }

    int g = lane >> 2, tig = lane & 3;
#pragma unroll
    for (int mt = 0; mt < 2; mt++)
#pragma unroll
        for (int hf = 0; hf < 2; hf++) {
            int row = m0 + wm * 32 + mt * 16 + g + hf * 8;
#pragma unroll
            for (int nt = 0; nt < 4; nt++) {
                int cb = wn * 32 + nt * 8 + tig * 2;
                float ox = acc[mt][nt][hf * 2 + 0] + sbias[cb];
                float oy = acc[mt][nt][hf * 2 + 1] + sbias[cb + 1];
                size_t e = (size_t)row * Ndim + n0 + cb;
                if (SPLIT) {
                    *(uint32_t*)(Ch + e) = pack_split_hi(ox, oy);
                    *(uint32_t*)(Cl + e) = pack_split_lo(ox, oy);
                } else {
                    float2 o; o.x = ox; o.y = oy;
                    *(float2*)(Cout + e) = o;
                }
            }
        }
}

// ---------------------------------------------------------------------------
// LayerNorm over rows of g_xr (4096 x 256); writes bf16 hi/lo splits.
// ---------------------------------------------------------------------------
__global__ __launch_bounds__(256) void layernorm_kernel(
    const float* __restrict__ g, const float* __restrict__ b)
{
    int warp = threadIdx.x >> 5, lane = threadIdx.x & 31;
    long row = (long)blockIdx.x * 8 + warp;
    const float* p = g_xr + row * 256;

    float4 v0 = ((const float4*)p)[lane];
    float4 v1 = ((const float4*)p)[lane + 32];
    float s  = v0.x + v0.y + v0.z + v0.w + v1.x + v1.y + v1.z + v1.w;
    float sq = v0.x * v0.x + v0.y * v0.y + v0.z * v0.z + v0.w * v0.w +
               v1.x * v1.x + v1.y * v1.y + v1.z * v1.z + v1.w * v1.w;
#pragma unroll
    for (int off = 16; off; off >>= 1) {
        s  += __shfl_xor_sync(0xffffffffu, s, off);
        sq += __shfl_xor_sync(0xffffffffu, sq, off);
    }
    float mu = s * (1.f / 256.f);
    float var = sq * (1.f / 256.f) - mu * mu;
    float rs = rsqrtf(var + 1e-5f);

    float4 g0 = ((const float4*)g)[lane];
    float4 b0 = ((const float4*)b)[lane];
    float4 g1 = ((const float4*)g)[lane + 32];
    float4 b1 = ((const float4*)b)[lane + 32];
    float o[8];
    o[0] = (v0.x - mu) * rs * g0.x + b0.x;
    o[1] = (v0.y - mu) * rs * g0.y + b0.y;
    o[2] = (v0.z - mu) * rs * g0.z + b0.z;
    o[3] = (v0.w - mu) * rs * g0.w + b0.w;
    o[4] = (v1.x - mu) * rs * g1.x + b1.x;
    o[5] = (v1.y - mu) * rs * g1.y + b1.y;
    o[6] = (v1.z - mu) * rs * g1.z + b1.z;
    o[7] = (v1.w - mu) * rs * g1.w + b1.w;

    long e0 = row * 256 + lane * 4;
    long e1 = row * 256 + (lane + 32) * 4;
#pragma unroll
    for (int half = 0; half < 2; half++) {
        long e = half ? e1 : e0;
        const float* ov = o + half * 4;
        *(uint32_t*)(g_xrh + e)     = pack_split_hi(ov[0], ov[1]);
        *(uint32_t*)(g_xrh + e + 2) = pack_split_hi(ov[2], ov[3]);
        *(uint32_t*)(g_xrl + e)     = pack_split_lo(ov[0], ov[1]);
        *(uint32_t*)(g_xrl + e + 2) = pack_split_lo(ov[2], ov[3]);
    }
}

// ---------------------------------------------------------------------------
// Flash attention v4: v3 + register-prefetch double buffering of K/V chunks.
// ---------------------------------------------------------------------------
__global__ __launch_bounds__(256) void attention_mma4_kernel() {
    __shared__ __nv_bfloat16 sQh[128 * AST], sQl[128 * AST];
    __shared__ __nv_bfloat16 sKh[32 * AST],  sKl[32 * AST];
    __shared__ __nv_bfloat16 sVth[32 * AST], sVtl[32 * AST];

    int tid = threadIdx.x, lane = tid & 31, wid = tid >> 5;
    int n0 = blockIdx.x * 128, h = blockIdx.y, b = blockIdx.z;
    int g = lane >> 2, tig = lane & 3;
    const float scale = 0.17677669529663689f;   // 1/sqrt(32)

    const __nv_bfloat16* QhG = g_qh  + ((long)b * Nn + n0) * Cc + h * 32;
    const __nv_bfloat16* QlG = g_ql  + ((long)b * Nn + n0) * Cc + h * 32;
    const __nv_bfloat16* KhG = g_kvh + (long)b * Mm * Cc + h * 32;          // k2
    const __nv_bfloat16* KlG = g_kvl + (long)b * Mm * Cc + h * 32;
    const __nv_bfloat16* VhG = g_kvh + BMC + (long)b * Mm * Cc + h * 32;    // v1
    const __nv_bfloat16* VlG = g_kvl + BMC + (long)b * Mm * Cc + h * 32;

    // Load Q tile (128 x 32) hi/lo into smem
    {
        int r = tid >> 1, hf = tid & 1;
        const __nv_bfloat16* qs = QhG + (long)r * Cc + hf * 16;
        *(uint4*)&sQh[r * AST + hf * 16]     = *(const uint4*)(qs);
        *(uint4*)&sQh[r * AST + hf * 16 + 8] = *(const uint4*)(qs + 8);
        const __nv_bfloat16* qsl = QlG + (long)r * Cc + hf * 16;
        *(uint4*)&sQl[r * AST + hf * 16]     = *(const uint4*)(qsl);
        *(uint4*)&sQl[r * AST + hf * 16 + 8] = *(const uint4*)(qsl + 8);
    }
    __syncthreads();

    // Persistent Q a-frags
    uint32_t qh[2][4], ql[2][4];
    {
        int a_row = wid * 16 + (lane & 15);
        int a_colb = (lane >> 4) << 3;
        uint32_t sq_h = smem_u32(sQh), sq_l = smem_u32(sQl);
#pragma unroll
        for (int ks = 0; ks < 2; ks++) {
            uint32_t off = (uint32_t)((a_row * AST + ks * 16 + a_colb) * 2);
            LDSM_X4(qh[ks][0], qh[ks][1], qh[ks][2], qh[ks][3], sq_h + off);
            LDSM_X4(ql[ks][0], ql[ks][1], ql[ks][2], ql[ks][3], sq_l + off);
        }
    }

    float mrun[2] = {-1e30f, -1e30f}, lrun[2] = {0.f, 0.f};
    float O[4][4];
#pragma unroll
    for (int dt = 0; dt < 4; dt++)
#pragma unroll
        for (int e = 0; e < 4; e++) O[dt][e] = 0.f;

    uint32_t sk_h = smem_u32(sKh), sk_l = smem_u32(sKl);
    uint32_t sv_h = smem_u32(sVth), sv_l = smem_u32(sVtl);

    int b_row  = ((lane >> 4) << 3) + (lane & 7);
    int b_colb = ((lane >> 3) & 1) << 3;

    // K/V loader roles (fixed per thread)
    int kbuf = tid >> 6;               // K: 0 hi, 1 lo (tid<128)
    int ki = tid & 63, kr = ki >> 1, khf = ki & 1;
    const __nv_bfloat16* kSrc = (kbuf ? KlG : KhG) + (long)kr * Cc + khf * 16;
    __nv_bfloat16* kDst = kbuf ? sKl : sKh;
    int vbuf = tid >> 7;               // V: 0 hi, 1 lo (all threads)
    int vi = tid & 127, vk = vi & 31, vdg = vi >> 5;
    const __nv_bfloat16* vSrc = (vbuf ? VlG : VhG) + (long)vk * Cc + vdg * 8;
    __nv_bfloat16* vDst = vbuf ? sVtl : sVth;

    uint4 kp0, kp1, vp;
    // prologue: prefetch chunk 0
    if (tid < 128) {
        kp0 = *(const uint4*)(kSrc);
        kp1 = *(const uint4*)(kSrc + 8);
    }
    vp = *(const uint4*)(vSrc);

    for (int mc = 0; mc < Mm / 32; mc++) {
        // commit prefetched K/V chunk to smem
        if (tid < 128) {
            *(uint4*)&kDst[kr * AST + khf * 16]     = kp0;
            *(uint4*)&kDst[kr * AST + khf * 16 + 8] = kp1;
        }
        {
            const __nv_bfloat16* hv = (const __nv_bfloat16*)&vp;
#pragma unroll
            for (int j = 0; j < 8; j++)
                vDst[(vdg * 8 + j) * AST + vk] = hv[j];
        }
        __syncthreads();

        // prefetch next chunk (hidden under compute)
        if (mc + 1 < Mm / 32) {
            long co = (long)(mc + 1) * 32 * Cc;
            if (tid < 128) {
                kp0 = *(const uint4*)(kSrc + co);
                kp1 = *(const uint4*)(kSrc + co + 8);
            }
            vp = *(const uint4*)(vSrc + co);
        }

        // ---- S = Q @ K^T (3-pass split) ----
        float s[4][4];
#pragma unroll
        for (int nt = 0; nt < 4; nt++)
#pragma unroll
            for (int e = 0; e < 4; e++) s[nt][e] = 0.f;

#pragma unroll
        for (int ks = 0; ks < 2; ks++) {
            uint32_t kh[4][2], kl[4][2];
#pragma unroll
            for (int grp = 0; grp < 2; grp++) {
                uint32_t off = (uint32_t)(((grp * 16 + b_row) * AST + ks * 16 + b_colb) * 2);
                uint32_t r0, r1, r2, r3;
                LDSM_X4(r0, r1, r2, r3, sk_h + off);
                kh[grp * 2][0] = r0; kh[grp * 2][1] = r1;
                kh[grp * 2 + 1][0] = r2; kh[grp * 2 + 1][1] = r3;
                LDSM_X4(r0, r1, r2, r3, sk_l + off);
                kl[grp * 2][0] = r0; kl[grp * 2][1] = r1;
                kl[grp * 2 + 1][0] = r2; kl[grp * 2 + 1][1] = r3;
            }
#pragma unroll
            for (int nt = 0; nt < 4; nt++) {
                MMA_BF16(s[nt], qh[ks], kh[nt]);
                MMA_BF16(s[nt], qh[ks], kl[nt]);
                MMA_BF16(s[nt], ql[ks], kh[nt]);
            }
        }

        // ---- in-register online softmax ----
        float p[4][4];
#pragma unroll
        for (int rh = 0; rh < 2; rh++) {
            float mx = -1e30f;
#pragma unroll
            for (int nt = 0; nt < 4; nt++)
                mx = fmaxf(mx, fmaxf(s[nt][rh * 2] * scale,
                                     s[nt][rh * 2 + 1] * scale));
            mx = fmaxf(mx, __shfl_xor_sync(0xffffffffu, mx, 1));
            mx = fmaxf(mx, __shfl_xor_sync(0xffffffffu, mx, 2));
            float mnew = fmaxf(mrun[rh], mx);
            float alpha = __expf(mrun[rh] - mnew);
            mrun[rh] = mnew;
            float sum = 0.f;
#pragma unroll
            for (int nt = 0; nt < 4; nt++) {
                float p0 = __expf(s[nt][rh * 2] * scale - mnew);
                float p1 = __expf(s[nt][rh * 2 + 1] * scale - mnew);
                p[nt][rh * 2] = p0;
                p[nt][rh * 2 + 1] = p1;
                sum += p0 + p1;
            }
            sum += __shfl_xor_sync(0xffffffffu, sum, 1);
            sum += __shfl_xor_sync(0xffffffffu, sum, 2);
            lrun[rh] = lrun[rh] * alpha + sum;
#pragma unroll
            for (int dt = 0; dt < 4; dt++) {
                O[dt][rh * 2]     *= alpha;
                O[dt][rh * 2 + 1] *= alpha;
            }
        }

        // ---- O += P @ Vt ----
#pragma unroll
        for (int ks = 0; ks < 2; ks++) {
            uint32_t pah[4], pal[4];
            pah[0] = pack_split_hi(p[2 * ks][0], p[2 * ks][1]);
            pah[1] = pack_split_hi(p[2 * ks][2], p[2 * ks][3]);
            pah[2] = pack_split_hi(p[2 * ks + 1][0], p[2 * ks + 1][1]);
            pah[3] = pack_split_hi(p[2 * ks + 1][2], p[2 * ks + 1][3]);
            pal[0] = pack_split_lo(p[2 * ks][0], p[2 * ks][1]);
            pal[1] = pack_split_lo(p[2 * ks][2], p[2 * ks][3]);
            pal[2] = pack_split_lo(p[2 * ks + 1][0], p[2 * ks + 1][1]);
            pal[3] = pack_split_lo(p[2 * ks + 1][2], p[2 * ks + 1][3]);

            uint32_t vh[4][2], vl[4][2];
#pragma unroll
            for (int dblk = 0; dblk < 2; dblk++) {
                uint32_t off = (uint32_t)(((dblk * 16 + b_row) * AST + ks * 16 + b_colb) * 2);
                uint32_t r0, r1, r2, r3;
                LDSM_X4(r0, r1, r2, r3, sv_h + off);
                vh[dblk * 2][0] = r0; vh[dblk * 2][1] = r1;
                vh[dblk * 2 + 1][0] = r2; vh[dblk * 2 + 1][1] = r3;
                LDSM_X4(r0, r1, r2, r3, sv_l + off);
                vl[dblk * 2][0] = r0; vl[dblk * 2][1] = r1;
                vl[dblk * 2 + 1][0] = r2; vl[dblk * 2 + 1][1] = r3;
            }
#pragma unroll
            for (int dt = 0; dt < 4; dt++) {
                MMA_BF16(O[dt], pah, vh[dt]);
                MMA_BF16(O[dt], pah, vl[dt]);
                MMA_BF16(O[dt], pal, vh[dt]);
            }
        }
        __syncthreads();
    }

    // ---- epilogue: normalize + split to bf16 hi/lo ----
    long base = ((long)b * Nn + n0) * Cc + h * 32;
#pragma unroll
    for (int rh = 0; rh < 2; rh++) {
        float inv = 1.f / lrun[rh];
        int row = wid * 16 + g + rh * 8;
#pragma unroll
        for (int dt = 0; dt < 4; dt++) {
            float ox = O[dt][rh * 2] * inv;
            float oy = O[dt][rh * 2 + 1] * inv;
            long e = base + (long)row * Cc + dt * 8 + tig * 2;
            *(uint32_t*)(g_ath + e) = pack_split_hi(ox, oy);
            *(uint32_t*)(g_atl + e) = pack_split_lo(ox, oy);
        }
    }
}

// ---------------------------------------------------------------------------
extern "C" void kernel_launch(void* const* d_in, const int* in_sizes, int n_in,
                              void* d_out, int out_size) {
    const float* x1     = (const float*)d_in[0];
    const float* x2     = (const float*)d_in[1];
    const float* q_w    = (const float*)d_in[2];
    const float* kv_w   = (const float*)d_in[3];
    const float* sr_w   = (const float*)d_in[4];
    const float* sr_b   = (const float*)d_in[5];
    const float* ln_g   = (const float*)d_in[6];
    const float* ln_b   = (const float*)d_in[7];
    const float* proj_w = (const float*)d_in[8];
    const float* proj_b = (const float*)d_in[9];
    float* out = (float*)d_out;

    float* p_xr;
    cudaGetSymbolAddress((void**)&p_xr, g_xr);
    __nv_bfloat16 *p_x1h, *p_x1l, *p_gah, *p_gal, *p_srh, *p_srl;
    __nv_bfloat16 *p_xrh, *p_xrl, *p_ath, *p_atl;
    __nv_bfloat16 *p_qh, *p_ql, *p_kvh, *p_kvl;
    __nv_bfloat16 *p_qwh, *p_qwl, *p_kwh, *p_kwl, *p_pwh, *p_pwl;
    cudaGetSymbolAddress((void**)&p_x1h, g_x1h);
    cudaGetSymbolAddress((void**)&p_x1l, g_x1l);
    cudaGetSymbolAddress((void**)&p_gah, g_gah);
    cudaGetSymbolAddress((void**)&p_gal, g_gal);
    cudaGetSymbolAddress((void**)&p_srh, g_srh);
    cudaGetSymbolAddress((void**)&p_srl, g_srl);
    cudaGetSymbolAddress((void**)&p_xrh, g_xrh);
    cudaGetSymbolAddress((void**)&p_xrl, g_xrl);
    cudaGetSymbolAddress((void**)&p_ath, g_ath);
    cudaGetSymbolAddress((void**)&p_atl, g_atl);
    cudaGetSymbolAddress((void**)&p_qh, g_qh);
    cudaGetSymbolAddress((void**)&p_ql, g_ql);
    cudaGetSymbolAddress((void**)&p_kvh, g_kvh);
    cudaGetSymbolAddress((void**)&p_kvl, g_kvl);
    cudaGetSymbolAddress((void**)&p_qwh, g_qwh);
    cudaGetSymbolAddress((void**)&p_qwl, g_qwl);
    cudaGetSymbolAddress((void**)&p_kwh, g_kwh);
    cudaGetSymbolAddress((void**)&p_kwl, g_kwl);
    cudaGetSymbolAddress((void**)&p_pwh, g_pwh);
    cudaGetSymbolAddress((void**)&p_pwl, g_pwl);

    // 1) fused prep (weights + inputs)
    prep_weights_kernel<<<1280, 256>>>(sr_w, q_w, kv_w, proj_w);
    prep_inputs_kernel<<<6144, 256>>>(x1, x2);

    // 2) q = x1 @ q_w^T  -> bf16 hi/lo
    gemm_mma_kernel<true><<<dim3(64, 4), 256>>>(
        p_x1h, p_x1l, p_qwh, p_qwl, nullptr, nullptr, p_qh, p_ql,
        Cc, Cc, 0, 0, 0);
    // 3) conv-as-GEMM + bias -> fp32 (pre-LN)
    gemm_mma_kernel<false><<<dim3(32, 4), 256>>>(
        p_gah, p_gal, p_srh, p_srl, sr_b, p_xr, nullptr, nullptr,
        Cc, Kc, 0, 0, 0);
    // 4) layernorm -> bf16 splits
    layernorm_kernel<<<512, 256>>>(ln_g, ln_b);
    // 5) batched: z=0: k2 = x2r @ kv_w[0:256]^T ; z=1: v1 = x1r @ kv_w[256:]^T
    gemm_mma_kernel<true><<<dim3(16, 4, 2), 256>>>(
        p_xrh + BMC, p_xrl + BMC, p_kwh, p_kwl,
        nullptr, nullptr, p_kvh, p_kvl,
        Cc, Cc, -BMC, (long)Cc * Cc, BMC);
    // 6) flash attention v4 (prefetch double-buffered) -> bf16 splits
    attention_mma4_kernel<<<dim3(Nn / 128, Hh, Bb), 256>>>();
    // 7) out = attn @ proj_w^T + proj_b
    gemm_mma_kernel<false><<<dim3(64, 4), 256>>>(
        p_ath, p_atl, p_pwh, p_pwl, proj_b, out, nullptr, nullptr,
        Cc, Cc, 0, 0, 0);
}